// round 5
// baseline (speedup 1.0000x reference)
#include <cuda_runtime.h>
#include <cstdint>
#include <cstddef>

// Problem constants
#define B_   32
#define S_   64
#define DM   256
#define KX   258        // D_MODEL + 2
#define KP   272        // padded K / smem row stride (17 chunks of 16)
#define H_   256
#define OUT_ 10

// ---------------- device scratch (static; no allocation) ----------------
__device__ float d_X[B_ * S_ * KP];     // concat(sentences, coord), zero padded
__device__ float d_AJ[B_ * S_ * H_];    // x[b,s] @ g_w1[0:258]
__device__ float d_AI[B_ * S_ * H_];    // x[b,s] @ g_w1[258:516]
__device__ float d_PART[B_ * S_ * H_];  // per-(b,i) partial row sums of h3

// ---------------- kernel A: build X ----------------
__global__ void k_build_x(const float* __restrict__ sent,
                          const float* __restrict__ coord) {
    int idx = blockIdx.x * 256 + threadIdx.x;
    if (idx >= B_ * S_ * KP) return;
    int k  = idx % KP;
    int bs = idx / KP;
    float v = 0.f;
    if (k < 256)      v = sent[bs * 256 + k];
    else if (k < 258) v = coord[bs * 2 + (k - 256)];
    d_X[idx] = v;
}

// ---------------- kernel B: precompute AJ, AI ----------------
__global__ void __launch_bounds__(256) k_precompute(const float* __restrict__ gw1) {
    __shared__ float Xs[16 * KP];
    int r0  = blockIdx.x * 16;            // 16 (b,s) rows per block
    int tid = threadIdx.x;                // tid == output channel h
    for (int t = tid; t < 16 * KP; t += 256) Xs[t] = d_X[r0 * KP + t];
    __syncthreads();

    float accJ[16], accI[16];
#pragma unroll
    for (int s = 0; s < 16; s++) { accJ[s] = 0.f; accI[s] = 0.f; }

#pragma unroll 2
    for (int k = 0; k < KX; k++) {
        float wj = gw1[k * H_ + tid];
        float wi = gw1[(KX + k) * H_ + tid];
#pragma unroll
        for (int s = 0; s < 16; s++) {
            float xv = Xs[s * KP + k];
            accJ[s] += xv * wj;
            accI[s] += xv * wi;
        }
    }
#pragma unroll
    for (int s = 0; s < 16; s++) {
        d_AJ[(r0 + s) * H_ + tid] = accJ[s];
        d_AI[(r0 + s) * H_ + tid] = accI[s];
    }
}

// ---------------- fused GEMM tile: 64x256, K streamed in 16-chunks ----------------
// A operand in smem (row stride KP). Weights streamed from global (L2-resident),
// double-buffered in smem; optionally scaled per-k by xi (folds x_i into Wc).
template <bool SCALE>
__device__ __forceinline__ void gemm_tile(
    float (&acc)[8][8],
    const float* __restrict__ Asm,     // smem, 64 x KP
    const float* __restrict__ Wg,      // global, [kvalid x 256] row-major
    int kvalid, int nchunks,
    float* __restrict__ wbuf,          // smem, 2 x 16 x 256
    const float* __restrict__ xi_s,    // smem, KP (zero padded)
    int tid, int tm, int tn)
{
#pragma unroll
    for (int r = 0; r < 8; r++)
#pragma unroll
        for (int c = 0; c < 8; c++) acc[r][c] = 0.f;

    // prologue: chunk 0 -> buffer 0  (kvalid >= 16 always here)
#pragma unroll
    for (int kk = 0; kk < 16; kk++) {
        float v = Wg[kk * H_ + tid];
        if (SCALE) v *= xi_s[kk];
        wbuf[kk * H_ + tid] = v;
    }
    __syncthreads();

    const float* Arow = Asm + tm * 8 * KP;

    for (int c = 0; c < nchunks; c++) {
        float st[16];
        bool more = (c + 1 < nchunks);
        if (more) {
            int kb2 = (c + 1) * 16;
#pragma unroll
            for (int kk = 0; kk < 16; kk++) {
                int k = kb2 + kk;
                float v = (k < kvalid) ? Wg[(size_t)k * H_ + tid] : 0.f;
                if (SCALE) v *= xi_s[k];
                st[kk] = v;
            }
        }
        const float* wb = wbuf + (c & 1) * (16 * H_);
        int kb = c * 16;
#pragma unroll
        for (int kk = 0; kk < 16; kk++) {
            float a[8];
#pragma unroll
            for (int r = 0; r < 8; r++) a[r] = Arow[r * KP + kb + kk];
            float4 b0 = *(const float4*)(wb + kk * H_ + tn * 8);
            float4 b1 = *(const float4*)(wb + kk * H_ + tn * 8 + 4);
            float bv[8] = {b0.x, b0.y, b0.z, b0.w, b1.x, b1.y, b1.z, b1.w};
#pragma unroll
            for (int r = 0; r < 8; r++)
#pragma unroll
                for (int cc = 0; cc < 8; cc++)
                    acc[r][cc] += a[r] * bv[cc];
        }
        if (more) {
            float* wn = wbuf + ((c + 1) & 1) * (16 * H_);
#pragma unroll
            for (int kk = 0; kk < 16; kk++) wn[kk * H_ + tid] = st[kk];
        }
        __syncthreads();
    }
}

// ---------------- kernel C: main fused chain, one CTA per (b,i) ----------------
__global__ void __launch_bounds__(256, 1) k_main(
    const float* __restrict__ gw1, const float* __restrict__ gb1,
    const float* __restrict__ gw2, const float* __restrict__ gb2,
    const float* __restrict__ gw3, const float* __restrict__ gb3)
{
    extern __shared__ float sm[];
    float* bufA = sm;                     // 64*KP = 17408 floats
    float* bufB = bufA + S_ * KP;         // 17408 floats
    float* wbuf = bufB + S_ * KP;         // 2*16*256 = 8192 floats
    float* xi_s = wbuf + 2 * 16 * H_;     // 272 floats
    float* aib  = xi_s + KP;              // 256 floats

    int tid = threadIdx.x;
    int tm = tid >> 5, tn = tid & 31;
    int b = blockIdx.x >> 6, i = blockIdx.x & 63;

    const float* Xb = d_X + (size_t)b * S_ * KP;

    // load X[b] tile (64 x 272 floats == 4352 float4 == 17 per thread)
    {
        float4* dst = (float4*)bufA;
        const float4* src = (const float4*)Xb;
#pragma unroll
        for (int t = 0; t < 17; t++) dst[tid + t * 256] = src[tid + t * 256];
    }
    for (int k = tid; k < KP; k += 256) xi_s[k] = Xb[i * KP + k];
    aib[tid] = d_AI[(size_t)(b * S_ + i) * H_ + tid] + gb1[tid];
    __syncthreads();

    float acc[8][8];

    // ---- layer 1: cross term GEMM (Wc rows pre-scaled by x_i during staging) ----
    gemm_tile<true>(acc, bufA, gw1 + 516 * H_, KX, 17, wbuf, xi_s, tid, tm, tn);
    {
        const float* AJb = d_AJ + (size_t)b * S_ * H_;
        float ab[8];
#pragma unroll
        for (int c = 0; c < 8; c++) ab[c] = aib[tn * 8 + c];
#pragma unroll
        for (int r = 0; r < 8; r++) {
            int j = tm * 8 + r;
            float4 a0 = *(const float4*)(AJb + (size_t)j * H_ + tn * 8);
            float4 a1 = *(const float4*)(AJb + (size_t)j * H_ + tn * 8 + 4);
            float v0 = fmaxf(acc[r][0] + a0.x + ab[0], 0.f);
            float v1 = fmaxf(acc[r][1] + a0.y + ab[1], 0.f);
            float v2 = fmaxf(acc[r][2] + a0.z + ab[2], 0.f);
            float v3 = fmaxf(acc[r][3] + a0.w + ab[3], 0.f);
            float v4 = fmaxf(acc[r][4] + a1.x + ab[4], 0.f);
            float v5 = fmaxf(acc[r][5] + a1.y + ab[5], 0.f);
            float v6 = fmaxf(acc[r][6] + a1.z + ab[6], 0.f);
            float v7 = fmaxf(acc[r][7] + a1.w + ab[7], 0.f);
            *(float4*)(bufB + j * KP + tn * 8)     = make_float4(v0, v1, v2, v3);
            *(float4*)(bufB + j * KP + tn * 8 + 4) = make_float4(v4, v5, v6, v7);
        }
    }
    // (ordering of bufB writes vs reads is guaranteed by gemm_tile's prologue sync)

    // ---- layer 2 ----
    gemm_tile<false>(acc, bufB, gw2, H_, 16, wbuf, xi_s, tid, tm, tn);
    {
        float bb[8];
#pragma unroll
        for (int c = 0; c < 8; c++) bb[c] = gb2[tn * 8 + c];
#pragma unroll
        for (int r = 0; r < 8; r++) {
            int j = tm * 8 + r;
            float v0 = fmaxf(acc[r][0] + bb[0], 0.f);
            float v1 = fmaxf(acc[r][1] + bb[1], 0.f);
            float v2 = fmaxf(acc[r][2] + bb[2], 0.f);
            float v3 = fmaxf(acc[r][3] + bb[3], 0.f);
            float v4 = fmaxf(acc[r][4] + bb[4], 0.f);
            float v5 = fmaxf(acc[r][5] + bb[5], 0.f);
            float v6 = fmaxf(acc[r][6] + bb[6], 0.f);
            float v7 = fmaxf(acc[r][7] + bb[7], 0.f);
            *(float4*)(bufA + j * KP + tn * 8)     = make_float4(v0, v1, v2, v3);
            *(float4*)(bufA + j * KP + tn * 8 + 4) = make_float4(v4, v5, v6, v7);
        }
    }

    // ---- layer 3 + row reduction ----
    gemm_tile<false>(acc, bufA, gw3, H_, 16, wbuf, xi_s, tid, tm, tn);
    {
        float bb[8];
#pragma unroll
        for (int c = 0; c < 8; c++) bb[c] = gb3[tn * 8 + c];
        float rs[8] = {0.f, 0.f, 0.f, 0.f, 0.f, 0.f, 0.f, 0.f};
#pragma unroll
        for (int r = 0; r < 8; r++)
#pragma unroll
            for (int c = 0; c < 8; c++)
                rs[c] += fmaxf(acc[r][c] + bb[c], 0.f);
        *(float4*)(bufB + tm * KP + tn * 8)     = make_float4(rs[0], rs[1], rs[2], rs[3]);
        *(float4*)(bufB + tm * KP + tn * 8 + 4) = make_float4(rs[4], rs[5], rs[6], rs[7]);
        __syncthreads();
        float s = 0.f;
#pragma unroll
        for (int t = 0; t < 8; t++) s += bufB[t * KP + tid];
        d_PART[(size_t)blockIdx.x * H_ + tid] = s;   // blockIdx.x == b*64 + i
    }
}

// ---------------- kernel D: reduce over i + final MLP ----------------
__global__ void __launch_bounds__(256) k_final(
    const float* __restrict__ fw1, const float* __restrict__ fb1,
    const float* __restrict__ fw2, const float* __restrict__ fb2,
    const float* __restrict__ fw3, const float* __restrict__ fb3,
    float* __restrict__ out)
{
    __shared__ float s0[H_], s1[H_], s2[H_];
    int b = blockIdx.x, t = threadIdx.x;

    const float* P = d_PART + (size_t)b * S_ * H_;
    float s = 0.f;
#pragma unroll 8
    for (int i = 0; i < S_; i++) s += P[i * H_ + t];
    s0[t] = s;
    __syncthreads();

    float a = fb1[t];
#pragma unroll 4
    for (int k = 0; k < H_; k++) a += s0[k] * fw1[k * H_ + t];
    s1[t] = fmaxf(a, 0.f);
    __syncthreads();

    a = fb2[t];
#pragma unroll 4
    for (int k = 0; k < H_; k++) a += s1[k] * fw2[k * H_ + t];
    s2[t] = fmaxf(a, 0.f);
    __syncthreads();

    if (t < OUT_) {
        a = fb3[t];
#pragma unroll 4
        for (int k = 0; k < H_; k++) a += s2[k] * fw3[k * OUT_ + t];
        out[b * OUT_ + t] = a;
    }
}

// ---------------- launch ----------------
extern "C" void kernel_launch(void* const* d_in, const int* in_sizes, int n_in,
                              void* d_out, int out_size) {
    const float* sent  = (const float*)d_in[0];
    const float* coord = (const float*)d_in[1];
    const float* gw1   = (const float*)d_in[2];
    const float* gb1   = (const float*)d_in[3];
    const float* gw2   = (const float*)d_in[4];
    const float* gb2   = (const float*)d_in[5];
    const float* gw3   = (const float*)d_in[6];
    const float* gb3   = (const float*)d_in[7];
    const float* fw1   = (const float*)d_in[8];
    const float* fb1   = (const float*)d_in[9];
    const float* fw2   = (const float*)d_in[10];
    const float* fb2   = (const float*)d_in[11];
    const float* fw3   = (const float*)d_in[12];
    const float* fb3   = (const float*)d_in[13];
    float* out = (float*)d_out;

    int nx = B_ * S_ * KP;
    k_build_x<<<(nx + 255) / 256, 256>>>(sent, coord);
    k_precompute<<<(B_ * S_) / 16, 256>>>(gw1);

    size_t smem = (size_t)(2 * S_ * KP + 2 * 16 * H_ + KP + H_) * sizeof(float);
    cudaFuncSetAttribute(k_main, cudaFuncAttributeMaxDynamicSharedMemorySize, (int)smem);
    k_main<<<B_ * S_, 256, smem>>>(gw1, gb1, gw2, gb2, gw3, gb3);

    k_final<<<B_, 256>>>(fw1, fb1, fw2, fb2, fw3, fb3, out);
}

// round 6
// speedup vs baseline: 1.4203x; 1.4203x over previous
#include <cuda_runtime.h>
#include <cstdint>
#include <cstddef>

// Problem constants
#define B_   32
#define S_   64
#define KX   258        // D_MODEL + 2
#define SA   268        // A-operand smem row stride (floats) — conflict-free (268%32=12)
#define SB   264        // W-chunk smem row stride (floats) — conflict-free (264%32=8)
#define K1P  264        // layer-1 K padded to 33 chunks of 8
#define H_   256
#define OUT_ 10
#define WCHUNK (8 * SB) // floats per W chunk buffer

// ---------------- device scratch (static; no allocation) ----------------
__device__ float d_X[B_ * S_ * SA];     // concat(sentences, coord), fp32, zero padded
__device__ float d_AJ[B_ * S_ * H_];    // x[b,s] @ g_w1[0:258]
__device__ float d_AI[B_ * S_ * H_];    // x[b,s] @ g_w1[258:516]
__device__ float d_PART[B_ * S_ * H_];  // per-(b,i) row sums of h3

// ---------------- helpers ----------------
__device__ __forceinline__ float tf32r(float x) {
    uint32_t u = __float_as_uint(x), r;
    asm("cvt.rna.tf32.f32 %0, %1;" : "=r"(r) : "r"(u));
    return __uint_as_float(r);
}

__device__ __forceinline__ void mma8(float (&d)[4], const uint32_t (&a)[4],
                                     const uint32_t (&b)[2]) {
    asm volatile(
        "mma.sync.aligned.m16n8k8.row.col.f32.tf32.tf32.f32 "
        "{%0,%1,%2,%3}, {%4,%5,%6,%7}, {%8,%9}, {%0,%1,%2,%3};"
        : "+f"(d[0]), "+f"(d[1]), "+f"(d[2]), "+f"(d[3])
        : "r"(a[0]), "r"(a[1]), "r"(a[2]), "r"(a[3]), "r"(b[0]), "r"(b[1]));
}

// ---------------- kernel A: build X (fp32, stride SA, zero padded) ----------------
__global__ void k_build_x(const float* __restrict__ sent,
                          const float* __restrict__ coord) {
    int idx = blockIdx.x * 256 + threadIdx.x;
    if (idx >= B_ * S_ * SA) return;
    int k  = idx % SA;
    int bs = idx / SA;
    float v = 0.f;
    if (k < 256)      v = sent[bs * 256 + k];
    else if (k < 258) v = coord[bs * 2 + (k - 256)];
    d_X[idx] = v;
}

// ---------------- kernel B: precompute AJ, AI (full fp32) ----------------
__global__ void __launch_bounds__(256) k_precompute(const float* __restrict__ gw1) {
    __shared__ float Xs[16 * SA];
    int r0  = blockIdx.x * 16;
    int tid = threadIdx.x;
    for (int t = tid; t < 16 * SA; t += 256) Xs[t] = d_X[r0 * SA + t];
    __syncthreads();

    float accJ[16], accI[16];
#pragma unroll
    for (int s = 0; s < 16; s++) { accJ[s] = 0.f; accI[s] = 0.f; }

#pragma unroll 2
    for (int k = 0; k < KX; k++) {
        float wj = gw1[k * H_ + tid];
        float wi = gw1[(KX + k) * H_ + tid];
#pragma unroll
        for (int s = 0; s < 16; s++) {
            float xv = Xs[s * SA + k];
            accJ[s] += xv * wj;
            accI[s] += xv * wi;
        }
    }
#pragma unroll
    for (int s = 0; s < 16; s++) {
        d_AJ[(r0 + s) * H_ + tid] = accJ[s];
        d_AI[(r0 + s) * H_ + tid] = accI[s];
    }
}

// ---------------- tensor-core GEMM tile: 64x256, K in chunks of 8 ----------------
// A (tf32-rounded) in smem [64 x SA]. W streamed from global fp32 (L2-resident),
// rounded (and optionally scaled by xi) while staging into double-buffered smem.
template <bool SCALE>
__device__ __forceinline__ void gemm_mma(
    float (&acc)[2][8][4],
    const float* __restrict__ Asm,
    const float* __restrict__ Wg,      // global fp32 [kvalid x 256]
    int kvalid, int nchunks,
    float* __restrict__ wbuf,          // smem, 2 x 8 x SB
    const float* __restrict__ xi_s,
    int tid, int wm, int wn, int g, int cth)
{
#pragma unroll
    for (int mi = 0; mi < 2; mi++)
#pragma unroll
        for (int ni = 0; ni < 8; ni++)
#pragma unroll
            for (int q = 0; q < 4; q++) acc[mi][ni][q] = 0.f;

    // prologue: chunk 0 -> buffer 0 (kvalid >= 8 always)
#pragma unroll
    for (int kk = 0; kk < 8; kk++) {
        float v = Wg[kk * H_ + tid];
        if (SCALE) v *= xi_s[kk];
        wbuf[kk * SB + tid] = tf32r(v);
    }
    __syncthreads();

    for (int c = 0; c < nchunks; c++) {
        float st[8];
        bool more = (c + 1 < nchunks);
        if (more) {
            int kb2 = (c + 1) * 8;
#pragma unroll
            for (int kk = 0; kk < 8; kk++) {
                int k = kb2 + kk;
                float v = (k < kvalid) ? Wg[(size_t)k * H_ + tid] : 0.f;
                if (SCALE) v *= xi_s[k];
                st[kk] = tf32r(v);
            }
        }
        const float* wb = wbuf + (c & 1) * WCHUNK;
        int kb = c * 8;

        uint32_t a[2][4];
#pragma unroll
        for (int mi = 0; mi < 2; mi++) {
            const float* Ar = Asm + (wm * 32 + mi * 16 + g) * SA + kb;
            a[mi][0] = __float_as_uint(Ar[cth]);
            a[mi][1] = __float_as_uint(Ar[8 * SA + cth]);
            a[mi][2] = __float_as_uint(Ar[cth + 4]);
            a[mi][3] = __float_as_uint(Ar[8 * SA + cth + 4]);
        }
#pragma unroll
        for (int ni = 0; ni < 8; ni++) {
            int col = wn * 64 + ni * 8 + g;
            uint32_t b[2];
            b[0] = __float_as_uint(wb[cth * SB + col]);
            b[1] = __float_as_uint(wb[(cth + 4) * SB + col]);
            mma8(acc[0][ni], a[0], b);
            mma8(acc[1][ni], a[1], b);
        }
        if (more) {
            float* wnx = wbuf + ((c + 1) & 1) * WCHUNK;
#pragma unroll
            for (int kk = 0; kk < 8; kk++) wnx[kk * SB + tid] = st[kk];
        }
        __syncthreads();
    }
}

// ---------------- kernel C: main fused chain, one CTA per (b,i) ----------------
__global__ void __launch_bounds__(256, 1) k_main(
    const float* __restrict__ gw1, const float* __restrict__ gb1,
    const float* __restrict__ gw2, const float* __restrict__ gb2,
    const float* __restrict__ gw3, const float* __restrict__ gb3)
{
    extern __shared__ float sm[];
    float* bufA = sm;                       // 64*SA
    float* bufB = bufA + S_ * SA;           // 64*SA
    float* wbuf = bufB + S_ * SA;           // 2*8*SB
    float* xi_s = wbuf + 2 * WCHUNK;        // SA
    float* aib  = xi_s + SA;                // 256: AI + b1
    float* b2s  = aib + H_;                 // 256
    float* b3s  = b2s + H_;                 // 256

    int tid = threadIdx.x;
    int w   = tid >> 5, lane = tid & 31;
    int wm  = w >> 2, wn = w & 3;           // warp tile: rows [wm*32,+32), cols [wn*64,+64)
    int g   = lane >> 2, cth = lane & 3;    // groupID, thread-in-group
    int b = blockIdx.x >> 6, i = blockIdx.x & 63;

    const float* Xb = d_X + (size_t)b * S_ * SA;

    // load X[b] tile, rounded to tf32 (A operand for layer 1)
    {
        const float4* src = (const float4*)Xb;
        float4* dst = (float4*)bufA;
        for (int t = tid; t < S_ * SA / 4; t += 256) {
            float4 v = src[t];
            v.x = tf32r(v.x); v.y = tf32r(v.y); v.z = tf32r(v.z); v.w = tf32r(v.w);
            dst[t] = v;
        }
    }
    for (int k = tid; k < SA; k += 256) xi_s[k] = Xb[i * SA + k];   // full fp32
    aib[tid] = d_AI[(size_t)(b * S_ + i) * H_ + tid] + gb1[tid];
    b2s[tid] = gb2[tid];
    b3s[tid] = gb3[tid];
    __syncthreads();

    float acc[2][8][4];

    // ---- layer 1: cross GEMM (W rows scaled by x_i at staging) ----
    gemm_mma<true>(acc, bufA, gw1 + 516 * H_, KX, K1P / 8, wbuf, xi_s,
                   tid, wm, wn, g, cth);
    {
        const float* AJb = d_AJ + (size_t)b * S_ * H_;
#pragma unroll
        for (int mi = 0; mi < 2; mi++) {
            int r = wm * 32 + mi * 16 + g;
#pragma unroll
            for (int ni = 0; ni < 8; ni++) {
                int c0 = wn * 64 + ni * 8 + 2 * cth;
                float a0 = aib[c0], a1 = aib[c0 + 1];
                float v00 = tf32r(fmaxf(acc[mi][ni][0] + AJb[r * H_ + c0] + a0, 0.f));
                float v01 = tf32r(fmaxf(acc[mi][ni][1] + AJb[r * H_ + c0 + 1] + a1, 0.f));
                float v10 = tf32r(fmaxf(acc[mi][ni][2] + AJb[(r + 8) * H_ + c0] + a0, 0.f));
                float v11 = tf32r(fmaxf(acc[mi][ni][3] + AJb[(r + 8) * H_ + c0 + 1] + a1, 0.f));
                *(float2*)(bufB + r * SA + c0)       = make_float2(v00, v01);
                *(float2*)(bufB + (r + 8) * SA + c0) = make_float2(v10, v11);
            }
        }
    }
    // bufB visibility guaranteed by gemm_mma prologue __syncthreads

    // ---- layer 2 ----
    gemm_mma<false>(acc, bufB, gw2, H_, H_ / 8, wbuf, xi_s, tid, wm, wn, g, cth);
    {
#pragma unroll
        for (int mi = 0; mi < 2; mi++) {
            int r = wm * 32 + mi * 16 + g;
#pragma unroll
            for (int ni = 0; ni < 8; ni++) {
                int c0 = wn * 64 + ni * 8 + 2 * cth;
                float a0 = b2s[c0], a1 = b2s[c0 + 1];
                float v00 = tf32r(fmaxf(acc[mi][ni][0] + a0, 0.f));
                float v01 = tf32r(fmaxf(acc[mi][ni][1] + a1, 0.f));
                float v10 = tf32r(fmaxf(acc[mi][ni][2] + a0, 0.f));
                float v11 = tf32r(fmaxf(acc[mi][ni][3] + a1, 0.f));
                *(float2*)(bufA + r * SA + c0)       = make_float2(v00, v01);
                *(float2*)(bufA + (r + 8) * SA + c0) = make_float2(v10, v11);
            }
        }
    }

    // ---- layer 3 + row reduction ----
    gemm_mma<false>(acc, bufA, gw3, H_, H_ / 8, wbuf, xi_s, tid, wm, wn, g, cth);
    {
#pragma unroll
        for (int mi = 0; mi < 2; mi++) {
            int r = wm * 32 + mi * 16 + g;
#pragma unroll
            for (int ni = 0; ni < 8; ni++) {
                int c0 = wn * 64 + ni * 8 + 2 * cth;
                float a0 = b3s[c0], a1 = b3s[c0 + 1];
                float v00 = fmaxf(acc[mi][ni][0] + a0, 0.f);
                float v01 = fmaxf(acc[mi][ni][1] + a1, 0.f);
                float v10 = fmaxf(acc[mi][ni][2] + a0, 0.f);
                float v11 = fmaxf(acc[mi][ni][3] + a1, 0.f);
                *(float2*)(bufB + r * SA + c0)       = make_float2(v00, v01);
                *(float2*)(bufB + (r + 8) * SA + c0) = make_float2(v10, v11);
            }
        }
        __syncthreads();
        float s = 0.f;
#pragma unroll
        for (int rr = 0; rr < S_; rr++) s += bufB[rr * SA + tid];
        d_PART[(size_t)blockIdx.x * H_ + tid] = s;
    }
}

// ---------------- kernel D: reduce over i + final MLP (latency fixed) ----------------
__global__ void __launch_bounds__(256) k_final(
    const float* __restrict__ fw1, const float* __restrict__ fb1,
    const float* __restrict__ fw2, const float* __restrict__ fb2,
    const float* __restrict__ fw3, const float* __restrict__ fb3,
    float* __restrict__ out)
{
    __shared__ float s0[H_], s1[H_], s2[H_];
    __shared__ float wsm[32 * H_];
    int b = blockIdx.x, t = threadIdx.x;

    const float* P = d_PART + (size_t)b * S_ * H_;
    float s = 0.f;
#pragma unroll 8
    for (int i = 0; i < S_; i++) s += P[i * H_ + t];
    s0[t] = s;
    __syncthreads();

    // layer 1
    {
        float a0 = 0.f, a1 = 0.f, a2 = 0.f, a3 = 0.f;
        for (int kb = 0; kb < H_; kb += 32) {
            const float4* wsrc = (const float4*)(fw1 + (size_t)kb * H_);
            float4* wdst = (float4*)wsm;
#pragma unroll
            for (int q = 0; q < 8; q++) wdst[t + q * 256] = wsrc[t + q * 256];
            __syncthreads();
#pragma unroll
            for (int kk = 0; kk < 32; kk += 4) {
                a0 += s0[kb + kk]     * wsm[kk * H_ + t];
                a1 += s0[kb + kk + 1] * wsm[(kk + 1) * H_ + t];
                a2 += s0[kb + kk + 2] * wsm[(kk + 2) * H_ + t];
                a3 += s0[kb + kk + 3] * wsm[(kk + 3) * H_ + t];
            }
            __syncthreads();
        }
        s1[t] = fmaxf((a0 + a1) + (a2 + a3) + fb1[t], 0.f);
    }
    __syncthreads();

    // layer 2
    {
        float a0 = 0.f, a1 = 0.f, a2 = 0.f, a3 = 0.f;
        for (int kb = 0; kb < H_; kb += 32) {
            const float4* wsrc = (const float4*)(fw2 + (size_t)kb * H_);
            float4* wdst = (float4*)wsm;
#pragma unroll
            for (int q = 0; q < 8; q++) wdst[t + q * 256] = wsrc[t + q * 256];
            __syncthreads();
#pragma unroll
            for (int kk = 0; kk < 32; kk += 4) {
                a0 += s1[kb + kk]     * wsm[kk * H_ + t];
                a1 += s1[kb + kk + 1] * wsm[(kk + 1) * H_ + t];
                a2 += s1[kb + kk + 2] * wsm[(kk + 2) * H_ + t];
                a3 += s1[kb + kk + 3] * wsm[(kk + 3) * H_ + t];
            }
            __syncthreads();
        }
        s2[t] = fmaxf((a0 + a1) + (a2 + a3) + fb2[t], 0.f);
    }
    __syncthreads();

    // layer 3 (OUT=10): stage fw3 into smem, then 10 threads finish
    for (int q = t; q < H_ * OUT_; q += 256) wsm[q] = fw3[q];
    __syncthreads();
    if (t < OUT_) {
        float a0 = 0.f, a1 = 0.f, a2 = 0.f, a3 = 0.f;
#pragma unroll
        for (int k = 0; k < H_; k += 4) {
            a0 += s2[k]     * wsm[k * OUT_ + t];
            a1 += s2[k + 1] * wsm[(k + 1) * OUT_ + t];
            a2 += s2[k + 2] * wsm[(k + 2) * OUT_ + t];
            a3 += s2[k + 3] * wsm[(k + 3) * OUT_ + t];
        }
        out[b * OUT_ + t] = (a0 + a1) + (a2 + a3) + fb3[t];
    }
}

// ---------------- launch ----------------
extern "C" void kernel_launch(void* const* d_in, const int* in_sizes, int n_in,
                              void* d_out, int out_size) {
    const float* sent  = (const float*)d_in[0];
    const float* coord = (const float*)d_in[1];
    const float* gw1   = (const float*)d_in[2];
    const float* gb1   = (const float*)d_in[3];
    const float* gw2   = (const float*)d_in[4];
    const float* gb2   = (const float*)d_in[5];
    const float* gw3   = (const float*)d_in[6];
    const float* gb3   = (const float*)d_in[7];
    const float* fw1   = (const float*)d_in[8];
    const float* fb1   = (const float*)d_in[9];
    const float* fw2   = (const float*)d_in[10];
    const float* fb2   = (const float*)d_in[11];
    const float* fw3   = (const float*)d_in[12];
    const float* fb3   = (const float*)d_in[13];
    float* out = (float*)d_out;

    int nx = B_ * S_ * SA;
    k_build_x<<<(nx + 255) / 256, 256>>>(sent, coord);
    k_precompute<<<(B_ * S_) / 16, 256>>>(gw1);

    size_t smem = (size_t)(2 * S_ * SA + 2 * WCHUNK + SA + 3 * H_) * sizeof(float);
    cudaFuncSetAttribute(k_main, cudaFuncAttributeMaxDynamicSharedMemorySize, (int)smem);
    k_main<<<B_ * S_, 256, smem>>>(gw1, gb1, gw2, gb2, gw3, gb3);

    k_final<<<B_, 256>>>(fw1, fb1, fw2, fb2, fw3, fb3, out);
}

// round 7
// speedup vs baseline: 2.8711x; 2.0215x over previous
#include <cuda_runtime.h>
#include <cstdint>
#include <cstddef>

// Problem constants
#define B_   32
#define S_   64
#define KX   258        // D_MODEL + 2
#define SA   272        // d_X row stride (floats), zero padded
#define SH   292        // H (activation) smem stride: banks 4g+cth conflict-free
#define SBW  264        // wbuf stride: banks 8cth+g conflict-free
#define K1   288        // layer-1 K padded to 9 chunks of 32
#define H_   256
#define OUT_ 10
#define KC   32         // K chunk per sync
#define WBUFSZ (KC * SBW)

// ---------------- device scratch (static; no allocation) ----------------
__device__ __align__(16) float d_X[B_ * S_ * SA];
__device__ __align__(16) float d_AJ[B_ * S_ * H_];
__device__ __align__(16) float d_AI[B_ * S_ * H_];
__device__ __align__(16) float d_PART[B_ * S_ * H_];
__device__ __align__(16) float d_W1c[K1 * H_];   // tf32-rounded cross weights, zero-padded
__device__ __align__(16) float d_W2r[H_ * H_];   // tf32-rounded g_w2
__device__ __align__(16) float d_W3r[H_ * H_];   // tf32-rounded g_w3

// ---------------- helpers ----------------
__device__ __forceinline__ float tf32r(float x) {
    uint32_t u = __float_as_uint(x), r;
    asm("cvt.rna.tf32.f32 %0, %1;" : "=r"(r) : "r"(u));
    return __uint_as_float(r);
}

__device__ __forceinline__ void mma8(float (&d)[4], const uint32_t (&a)[4],
                                     const uint32_t (&b)[2]) {
    asm volatile(
        "mma.sync.aligned.m16n8k8.row.col.f32.tf32.tf32.f32 "
        "{%0,%1,%2,%3}, {%4,%5,%6,%7}, {%8,%9}, {%0,%1,%2,%3};"
        : "+f"(d[0]), "+f"(d[1]), "+f"(d[2]), "+f"(d[3])
        : "r"(a[0]), "r"(a[1]), "r"(a[2]), "r"(a[3]), "r"(b[0]), "r"(b[1]));
}

__device__ __forceinline__ void cpasync16(uint32_t s, const float* g) {
    asm volatile("cp.async.cg.shared.global [%0], [%1], 16;" :: "r"(s), "l"(g));
}
__device__ __forceinline__ void cp_commit() {
    asm volatile("cp.async.commit_group;");
}
__device__ __forceinline__ void cp_wait_all() {
    asm volatile("cp.async.wait_group 0;" ::: "memory");
}

// ---------------- kernel A: build X (fp32, stride SA, zero padded) ----------------
__global__ void k_build_x(const float* __restrict__ sent,
                          const float* __restrict__ coord) {
    int idx = blockIdx.x * 256 + threadIdx.x;
    if (idx >= B_ * S_ * SA) return;
    int k  = idx % SA;
    int bs = idx / SA;
    float v = 0.f;
    if (k < 256)      v = sent[bs * 256 + k];
    else if (k < 258) v = coord[bs * 2 + (k - 256)];
    d_X[idx] = v;
}

// ---------------- kernel A2: pre-round weights to tf32 ----------------
__global__ void k_roundw(const float* __restrict__ gw1,
                         const float* __restrict__ gw2,
                         const float* __restrict__ gw3) {
    int idx = blockIdx.x * 256 + threadIdx.x;
    if (idx < K1 * H_) {
        int r = idx / H_, c = idx % H_;
        d_W1c[idx] = (r < KX) ? tf32r(gw1[(size_t)(516 + r) * H_ + c]) : 0.f;
    } else if (idx < K1 * H_ + H_ * H_) {
        int j = idx - K1 * H_;
        d_W2r[j] = tf32r(gw2[j]);
    } else if (idx < K1 * H_ + 2 * H_ * H_) {
        int j = idx - K1 * H_ - H_ * H_;
        d_W3r[j] = tf32r(gw3[j]);
    }
}

// ---------------- kernel B: precompute AJ, AI (full fp32) ----------------
__global__ void __launch_bounds__(256) k_precompute(const float* __restrict__ gw1) {
    __shared__ float Xs[16 * SA];
    int r0  = blockIdx.x * 16;
    int tid = threadIdx.x;
    for (int t = tid; t < 16 * SA; t += 256) Xs[t] = d_X[r0 * SA + t];
    __syncthreads();

    float accJ[16], accI[16];
#pragma unroll
    for (int s = 0; s < 16; s++) { accJ[s] = 0.f; accI[s] = 0.f; }

#pragma unroll 2
    for (int k = 0; k < KX; k++) {
        float wj = gw1[k * H_ + tid];
        float wi = gw1[(KX + k) * H_ + tid];
#pragma unroll
        for (int s = 0; s < 16; s++) {
            float xv = Xs[s * SA + k];
            accJ[s] += xv * wj;
            accI[s] += xv * wi;
        }
    }
#pragma unroll
    for (int s = 0; s < 16; s++) {
        d_AJ[(r0 + s) * H_ + tid] = accJ[s];
        d_AI[(r0 + s) * H_ + tid] = accI[s];
    }
}

// ---------------- tensor GEMM: 128x256, A in smem (stride SH), W via cp.async ----
__device__ __forceinline__ void gemm32(
    float (&acc)[4][8][4],
    const float* __restrict__ Hs,
    float* __restrict__ wbuf, uint32_t wb_s32,
    const float* __restrict__ Wg, int nchunks,
    int srow, int scol, int wm, int wn, int g, int cth)
{
#pragma unroll
    for (int mi = 0; mi < 4; mi++)
#pragma unroll
        for (int ni = 0; ni < 8; ni++)
#pragma unroll
            for (int q = 0; q < 4; q++) acc[mi][ni][q] = 0.f;

    // issue chunk 0 -> buffer 0
    {
        uint32_t so = wb_s32 + (uint32_t)(srow * SBW + scol) * 4u;
        const float* gp = Wg + (size_t)srow * H_ + scol;
#pragma unroll
        for (int q = 0; q < 8; q++)
            cpasync16(so + q * (4u * SBW * 4u), gp + (size_t)q * 4 * H_);
        cp_commit();
    }

    for (int c = 0; c < nchunks; c++) {
        cp_wait_all();
        __syncthreads();
        if (c + 1 < nchunks) {
            uint32_t so = wb_s32 + (uint32_t)(((c + 1) & 1) * WBUFSZ) * 4u
                                 + (uint32_t)(srow * SBW + scol) * 4u;
            const float* gp = Wg + (size_t)(c + 1) * KC * H_ + (size_t)srow * H_ + scol;
#pragma unroll
            for (int q = 0; q < 8; q++)
                cpasync16(so + q * (4u * SBW * 4u), gp + (size_t)q * 4 * H_);
            cp_commit();
        }
        const float* wb = wbuf + (c & 1) * WBUFSZ;
        int kOff = c * KC;
#pragma unroll
        for (int ks = 0; ks < 4; ks++) {
            uint32_t a[4][4];
            const float* Ab = Hs + kOff + ks * 8;
#pragma unroll
            for (int mi = 0; mi < 4; mi++) {
                const float* Ar = Ab + (wm * 64 + mi * 16 + g) * SH;
                a[mi][0] = __float_as_uint(Ar[cth]);
                a[mi][1] = __float_as_uint(Ar[8 * SH + cth]);
                a[mi][2] = __float_as_uint(Ar[cth + 4]);
                a[mi][3] = __float_as_uint(Ar[8 * SH + cth + 4]);
            }
            const float* w0 = wb + (ks * 8 + cth) * SBW + wn * 64 + g;
            const float* w1 = wb + (ks * 8 + cth + 4) * SBW + wn * 64 + g;
#pragma unroll
            for (int ni = 0; ni < 8; ni++) {
                uint32_t b[2];
                b[0] = __float_as_uint(w0[ni * 8]);
                b[1] = __float_as_uint(w1[ni * 8]);
                mma8(acc[0][ni], a[0], b);
                mma8(acc[1][ni], a[1], b);
                mma8(acc[2][ni], a[2], b);
                mma8(acc[3][ni], a[3], b);
            }
        }
    }
}

// ---------------- kernel C: main fused chain, one CTA per (b, i-pair) ----------
__global__ void __launch_bounds__(256, 1) k_main(
    const float* __restrict__ gb1, const float* __restrict__ gb2,
    const float* __restrict__ gb3)
{
    extern __shared__ float sm[];
    float* Hs   = sm;                    // 128*SH
    float* wbuf = Hs + 128 * SH;         // 2*WBUFSZ
    float* xi_s = wbuf + 2 * WBUFSZ;     // 2*SA
    float* aib0 = xi_s + 2 * SA;         // 256
    float* aib1 = aib0 + H_;             // 256
    float* b2s  = aib1 + H_;             // 256
    float* b3s  = b2s + H_;              // 256

    int tid = threadIdx.x;
    int w = tid >> 5, lane = tid & 31;
    int wm = w >> 2, wn = w & 3;        // warp tile: rows [wm*64,+64), cols [wn*64,+64)
    int g = lane >> 2, cth = lane & 3;
    int b = blockIdx.x >> 5, ip = blockIdx.x & 31;
    int i0 = 2 * ip, i1 = 2 * ip + 1;

    // cp.async staging coords (constant per thread)
    int srow = tid >> 6;                // +4 per q
    int scol = (tid & 63) * 4;
    uint32_t wb_s32 = (uint32_t)__cvta_generic_to_shared(wbuf);

    const float* Xb = d_X + (size_t)b * S_ * SA;

    // prologue: xi rows, biases
    for (int k = tid; k < 2 * SA; k += 256) {
        int half = k >= SA, kk = k - half * SA;
        xi_s[k] = Xb[(size_t)(half ? i1 : i0) * SA + kk];
    }
    aib0[tid] = d_AI[(size_t)(b * S_ + i0) * H_ + tid] + gb1[tid];
    aib1[tid] = d_AI[(size_t)(b * S_ + i1) * H_ + tid] + gb1[tid];
    b2s[tid] = gb2[tid];
    b3s[tid] = gb3[tid];
    __syncthreads();

    // build P tile: P[r,k] = tf32(x_i[k] * x_j[k]), r=(half,j), cols 0..287
#pragma unroll 4
    for (int q = 0; q < 36; q++) {
        int idx = tid + q * 256;            // 0..9215 over 128 rows x 72 f4
        int r = idx / 72, k4 = idx % 72;
        int half = r >> 6, j = r & 63;
        float4 v;
        if (k4 < SA / 4) {
            float4 xj = *(const float4*)(Xb + (size_t)j * SA + k4 * 4);
            float4 xi = *(const float4*)(xi_s + half * SA + k4 * 4);
            v.x = tf32r(xj.x * xi.x); v.y = tf32r(xj.y * xi.y);
            v.z = tf32r(xj.z * xi.z); v.w = tf32r(xj.w * xi.w);
        } else {
            v = make_float4(0.f, 0.f, 0.f, 0.f);
        }
        *(float4*)(Hs + (size_t)r * SH + k4 * 4) = v;
    }
    // gemm's internal syncthreads (before first MMA) covers P visibility

    float acc[4][8][4];

    // ---- layer 1: pairs x Wc ----
    gemm32(acc, Hs, wbuf, wb_s32, d_W1c, K1 / KC, srow, scol, wm, wn, g, cth);
    {
        __syncthreads();   // all warps done reading H
        const float* AJb = d_AJ + (size_t)b * S_ * H_;
        const float* aibp = wm ? aib1 : aib0;
#pragma unroll
        for (int mi = 0; mi < 4; mi++) {
            int r = wm * 64 + mi * 16 + g;
            int j0 = r & 63, j1 = (r + 8) & 63;
#pragma unroll
            for (int ni = 0; ni < 8; ni++) {
                int c0 = wn * 64 + ni * 8 + 2 * cth;
                float a0 = aibp[c0], a1 = aibp[c0 + 1];
                float v00 = tf32r(fmaxf(acc[mi][ni][0] + AJb[(size_t)j0 * H_ + c0] + a0, 0.f));
                float v01 = tf32r(fmaxf(acc[mi][ni][1] + AJb[(size_t)j0 * H_ + c0 + 1] + a1, 0.f));
                float v10 = tf32r(fmaxf(acc[mi][ni][2] + AJb[(size_t)j1 * H_ + c0] + a0, 0.f));
                float v11 = tf32r(fmaxf(acc[mi][ni][3] + AJb[(size_t)j1 * H_ + c0 + 1] + a1, 0.f));
                *(float2*)(Hs + (size_t)r * SH + c0)       = make_float2(v00, v01);
                *(float2*)(Hs + (size_t)(r + 8) * SH + c0) = make_float2(v10, v11);
            }
        }
    }

    // ---- layer 2 ----
    gemm32(acc, Hs, wbuf, wb_s32, d_W2r, H_ / KC, srow, scol, wm, wn, g, cth);
    {
        __syncthreads();
#pragma unroll
        for (int mi = 0; mi < 4; mi++) {
            int r = wm * 64 + mi * 16 + g;
#pragma unroll
            for (int ni = 0; ni < 8; ni++) {
                int c0 = wn * 64 + ni * 8 + 2 * cth;
                float a0 = b2s[c0], a1 = b2s[c0 + 1];
                float v00 = tf32r(fmaxf(acc[mi][ni][0] + a0, 0.f));
                float v01 = tf32r(fmaxf(acc[mi][ni][1] + a1, 0.f));
                float v10 = tf32r(fmaxf(acc[mi][ni][2] + a0, 0.f));
                float v11 = tf32r(fmaxf(acc[mi][ni][3] + a1, 0.f));
                *(float2*)(Hs + (size_t)r * SH + c0)       = make_float2(v00, v01);
                *(float2*)(Hs + (size_t)(r + 8) * SH + c0) = make_float2(v10, v11);
            }
        }
    }

    // ---- layer 3 + row reduction ----
    gemm32(acc, Hs, wbuf, wb_s32, d_W3r, H_ / KC, srow, scol, wm, wn, g, cth);
    {
        __syncthreads();
#pragma unroll
        for (int mi = 0; mi < 4; mi++) {
            int r = wm * 64 + mi * 16 + g;
#pragma unroll
            for (int ni = 0; ni < 8; ni++) {
                int c0 = wn * 64 + ni * 8 + 2 * cth;
                float a0 = b3s[c0], a1 = b3s[c0 + 1];
                float v00 = fmaxf(acc[mi][ni][0] + a0, 0.f);
                float v01 = fmaxf(acc[mi][ni][1] + a1, 0.f);
                float v10 = fmaxf(acc[mi][ni][2] + a0, 0.f);
                float v11 = fmaxf(acc[mi][ni][3] + a1, 0.f);
                *(float2*)(Hs + (size_t)r * SH + c0)       = make_float2(v00, v01);
                *(float2*)(Hs + (size_t)(r + 8) * SH + c0) = make_float2(v10, v11);
            }
        }
        __syncthreads();
        float s0 = 0.f, s1 = 0.f;
#pragma unroll 8
        for (int rr = 0; rr < 64; rr++) {
            s0 += Hs[(size_t)rr * SH + tid];
            s1 += Hs[(size_t)(64 + rr) * SH + tid];
        }
        d_PART[(size_t)(b * S_ + i0) * H_ + tid] = s0;
        d_PART[(size_t)(b * S_ + i1) * H_ + tid] = s1;
    }
}

// ---------------- kernel D: reduce over i + final MLP ----------------
__global__ void __launch_bounds__(256) k_final(
    const float* __restrict__ fw1, const float* __restrict__ fb1,
    const float* __restrict__ fw2, const float* __restrict__ fb2,
    const float* __restrict__ fw3, const float* __restrict__ fb3,
    float* __restrict__ out)
{
    __shared__ float s0[H_], s1[H_], s2[H_];
    __shared__ float wsm[32 * H_];
    int b = blockIdx.x, t = threadIdx.x;

    const float* P = d_PART + (size_t)b * S_ * H_;
    float s = 0.f;
#pragma unroll 8
    for (int i = 0; i < S_; i++) s += P[i * H_ + t];
    s0[t] = s;
    __syncthreads();

    // layer 1
    {
        float a0 = 0.f, a1 = 0.f, a2 = 0.f, a3 = 0.f;
        for (int kb = 0; kb < H_; kb += 32) {
            const float4* wsrc = (const float4*)(fw1 + (size_t)kb * H_);
            float4* wdst = (float4*)wsm;
#pragma unroll
            for (int q = 0; q < 8; q++) wdst[t + q * 256] = wsrc[t + q * 256];
            __syncthreads();
#pragma unroll
            for (int kk = 0; kk < 32; kk += 4) {
                a0 += s0[kb + kk]     * wsm[kk * H_ + t];
                a1 += s0[kb + kk + 1] * wsm[(kk + 1) * H_ + t];
                a2 += s0[kb + kk + 2] * wsm[(kk + 2) * H_ + t];
                a3 += s0[kb + kk + 3] * wsm[(kk + 3) * H_ + t];
            }
            __syncthreads();
        }
        s1[t] = fmaxf((a0 + a1) + (a2 + a3) + fb1[t], 0.f);
    }
    __syncthreads();

    // layer 2
    {
        float a0 = 0.f, a1 = 0.f, a2 = 0.f, a3 = 0.f;
        for (int kb = 0; kb < H_; kb += 32) {
            const float4* wsrc = (const float4*)(fw2 + (size_t)kb * H_);
            float4* wdst = (float4*)wsm;
#pragma unroll
            for (int q = 0; q < 8; q++) wdst[t + q * 256] = wsrc[t + q * 256];
            __syncthreads();
#pragma unroll
            for (int kk = 0; kk < 32; kk += 4) {
                a0 += s1[kb + kk]     * wsm[kk * H_ + t];
                a1 += s1[kb + kk + 1] * wsm[(kk + 1) * H_ + t];
                a2 += s1[kb + kk + 2] * wsm[(kk + 2) * H_ + t];
                a3 += s1[kb + kk + 3] * wsm[(kk + 3) * H_ + t];
            }
            __syncthreads();
        }
        s2[t] = fmaxf((a0 + a1) + (a2 + a3) + fb2[t], 0.f);
    }
    __syncthreads();

    // layer 3 (OUT=10)
    for (int q = t; q < H_ * OUT_; q += 256) wsm[q] = fw3[q];
    __syncthreads();
    if (t < OUT_) {
        float a0 = 0.f, a1 = 0.f, a2 = 0.f, a3 = 0.f;
#pragma unroll
        for (int k = 0; k < H_; k += 4) {
            a0 += s2[k]     * wsm[k * OUT_ + t];
            a1 += s2[k + 1] * wsm[(k + 1) * OUT_ + t];
            a2 += s2[k + 2] * wsm[(k + 2) * OUT_ + t];
            a3 += s2[k + 3] * wsm[(k + 3) * OUT_ + t];
        }
        out[b * OUT_ + t] = (a0 + a1) + (a2 + a3) + fb3[t];
    }
}

// ---------------- launch ----------------
extern "C" void kernel_launch(void* const* d_in, const int* in_sizes, int n_in,
                              void* d_out, int out_size) {
    const float* sent  = (const float*)d_in[0];
    const float* coord = (const float*)d_in[1];
    const float* gw1   = (const float*)d_in[2];
    const float* gb1   = (const float*)d_in[3];
    const float* gw2   = (const float*)d_in[4];
    const float* gb2   = (const float*)d_in[5];
    const float* gw3   = (const float*)d_in[6];
    const float* gb3   = (const float*)d_in[7];
    const float* fw1   = (const float*)d_in[8];
    const float* fb1   = (const float*)d_in[9];
    const float* fw2   = (const float*)d_in[10];
    const float* fb2   = (const float*)d_in[11];
    const float* fw3   = (const float*)d_in[12];
    const float* fb3   = (const float*)d_in[13];
    float* out = (float*)d_out;

    int nx = B_ * S_ * SA;
    k_build_x<<<(nx + 255) / 256, 256>>>(sent, coord);
    int nw = K1 * H_ + 2 * H_ * H_;
    k_roundw<<<(nw + 255) / 256, 256>>>(gw1, gw2, gw3);
    k_precompute<<<(B_ * S_) / 16, 256>>>(gw1);

    size_t smem = (size_t)(128 * SH + 2 * WBUFSZ + 2 * SA + 4 * H_) * sizeof(float);
    cudaFuncSetAttribute(k_main, cudaFuncAttributeMaxDynamicSharedMemorySize, (int)smem);
    k_main<<<B_ * S_ / 2, 256, smem>>>(gb1, gb2, gb3);

    k_final<<<B_, 256>>>(fw1, fb1, fw2, fb2, fw3, fb3, out);
}

// round 9
// speedup vs baseline: 2.8959x; 1.0086x over previous
#include <cuda_runtime.h>
#include <cstdint>
#include <cstddef>

// Problem constants
#define B_   32
#define S_   64
#define KX   258        // D_MODEL + 2
#define SA   272        // d_X row stride (floats)
#define H_   256
#define OUT_ 10
#define K1   288        // layer-1 K padded (9 chunks of 32)
#define SAP  296        // A/activation smem row stride (296%32==8 -> 2-phase LDS.64)

// smem layout (floats)
#define OFF_WBUF  37888                   // A tile: 128*296
#define OFF_XI    (OFF_WBUF + 16384)      // 2 x 8192-float weight chunk buffers
#define OFF_AIB0  (OFF_XI + 544)
#define OFF_AIB1  (OFF_AIB0 + 256)
#define OFF_B2    (OFF_AIB1 + 256)
#define OFF_B3    (OFF_B2 + 256)
#define SMEM_FLOATS (OFF_B3 + 256)        // 55840 floats = 223360 B

// ---------------- device scratch (static; no allocation) ----------------
__device__ __align__(16) float d_X[B_ * S_ * SA];
__device__ __align__(16) float d_AJ[B_ * S_ * H_];
__device__ __align__(16) float d_AI[B_ * S_ * H_];
__device__ __align__(16) float d_PART[B_ * S_ * H_];
// weights pre-rounded to tf32 AND pre-arranged in per-thread MMA fragment order
__device__ __align__(16) float d_W1f[9 * 8192];
__device__ __align__(16) float d_W2f[8 * 8192];
__device__ __align__(16) float d_W3f[8 * 8192];

// ---------------- helpers ----------------
__device__ __forceinline__ float tf32r(float x) {
    uint32_t u = __float_as_uint(x), r;
    asm("cvt.rna.tf32.f32 %0, %1;" : "=r"(r) : "r"(u));
    return __uint_as_float(r);
}
__device__ __forceinline__ void mma8(float (&d)[4], const uint32_t (&a)[4],
                                     const uint32_t (&b)[2]) {
    asm volatile(
        "mma.sync.aligned.m16n8k8.row.col.f32.tf32.tf32.f32 "
        "{%0,%1,%2,%3}, {%4,%5,%6,%7}, {%8,%9}, {%0,%1,%2,%3};"
        : "+f"(d[0]), "+f"(d[1]), "+f"(d[2]), "+f"(d[3])
        : "r"(a[0]), "r"(a[1]), "r"(a[2]), "r"(a[3]), "r"(b[0]), "r"(b[1]));
}
__device__ __forceinline__ void cpasync16(uint32_t s, const float* g) {
    asm volatile("cp.async.cg.shared.global [%0], [%1], 16;" :: "r"(s), "l"(g));
}

// ---------------- kernel A: build X ----------------
__global__ void k_build_x(const float* __restrict__ sent,
                          const float* __restrict__ coord) {
    int idx = blockIdx.x * 256 + threadIdx.x;
    if (idx >= B_ * S_ * SA) return;
    int k  = idx % SA;
    int bs = idx / SA;
    float v = 0.f;
    if (k < 256)      v = sent[bs * 256 + k];
    else if (k < 258) v = coord[bs * 2 + (k - 256)];
    d_X[idx] = v;
}

// ---------------- kernel A2: weights -> tf32 fragment layout ----------------
// Fragment element (chunk c, f in [0,8192)): slot=f>>7, lane=(f&127)>>2, q=f&3
//   slot = ks*16 + wn*4 + np
//   k = c*32 + ks*8 + (lane&3) + (q&1)*4
//   n = wn*64 + (np*2 + (q>>1))*8 + (lane>>2)
__global__ void k_roundw(const float* __restrict__ gw1,
                         const float* __restrict__ gw2,
                         const float* __restrict__ gw3) {
    int idx = blockIdx.x * 256 + threadIdx.x;
    if (idx >= 9 * 8192 + 2 * 8 * 8192) return;
    int layer, e;
    if (idx < 9 * 8192)               { layer = 1; e = idx; }
    else if (idx < 9 * 8192 + 65536)  { layer = 2; e = idx - 9 * 8192; }
    else                              { layer = 3; e = idx - 9 * 8192 - 65536; }
    int c = e >> 13, f = e & 8191;
    int slot = f >> 7, r = f & 127;
    int lane = r >> 2, q = r & 3;
    int ks = slot >> 4, wn = (slot >> 2) & 3, np = slot & 3;
    int k = c * 32 + ks * 8 + (lane & 3) + (q & 1) * 4;
    int n = wn * 64 + (np * 2 + (q >> 1)) * 8 + (lane >> 2);
    if (layer == 1)
        d_W1f[e] = (k < KX) ? tf32r(gw1[(size_t)(516 + k) * H_ + n]) : 0.f;
    else if (layer == 2)
        d_W2f[e] = tf32r(gw2[(size_t)k * H_ + n]);
    else
        d_W3f[e] = tf32r(gw3[(size_t)k * H_ + n]);
}

// ---------------- kernel B: precompute AJ, AI (fp32) ----------------
__global__ void __launch_bounds__(256) k_precompute(const float* __restrict__ gw1) {
    __shared__ float Xs[16 * SA];
    int r0  = blockIdx.x * 16;
    int tid = threadIdx.x;
    for (int t = tid; t < 16 * SA; t += 256) Xs[t] = d_X[r0 * SA + t];
    __syncthreads();

    float accJ[16], accI[16];
#pragma unroll
    for (int s = 0; s < 16; s++) { accJ[s] = 0.f; accI[s] = 0.f; }

#pragma unroll 2
    for (int k = 0; k < KX; k++) {
        float wj = gw1[k * H_ + tid];
        float wi = gw1[(KX + k) * H_ + tid];
#pragma unroll
        for (int s = 0; s < 16; s++) {
            float xv = Xs[s * SA + k];
            accJ[s] += xv * wj;
            accI[s] += xv * wi;
        }
    }
#pragma unroll
    for (int s = 0; s < 16; s++) {
        d_AJ[(r0 + s) * H_ + tid] = accJ[s];
        d_AI[(r0 + s) * H_ + tid] = accI[s];
    }
}

// ---------------- weight chunk staging: pure linear 32KB copy ----------------
__device__ __forceinline__ void stage_chunk(uint32_t bdst, const float* __restrict__ W) {
    int tid = threadIdx.x;
#pragma unroll
    for (int it = 0; it < 8; it++) {
        int seg = tid + it * 256;
        cpasync16(bdst + (uint32_t)seg * 16u, W + (size_t)seg * 4);
    }
    asm volatile("cp.async.commit_group;");
}

// ---------------- fragment-layout GEMM: 128x256, KC=32 chunks ----------------
__device__ __forceinline__ void gemm_frag(
    float (&acc)[4][8][4],
    const float* __restrict__ Ap,       // smem, permuted-k rows, stride SAP
    const float* __restrict__ wbuf, uint32_t wb_s32,
    const float* __restrict__ W, int nch, int p0,
    const float* __restrict__ nextW,
    int wm, int wn, int g, int cth)
{
#pragma unroll
    for (int mi = 0; mi < 4; mi++)
#pragma unroll
        for (int ni = 0; ni < 8; ni++)
#pragma unroll
            for (int q = 0; q < 4; q++) acc[mi][ni][q] = 0.f;

    const float* Abase = Ap + (size_t)(wm * 64 + g) * SAP + 2 * cth;
    int lane = threadIdx.x & 31;

    for (int c = 0; c < nch; c++) {
        asm volatile("cp.async.wait_group 0;" ::: "memory");
        __syncthreads();
        if (c + 1 < nch)
            stage_chunk(wb_s32 + (uint32_t)(((c + 1 + p0) & 1)) * 32768u,
                        W + (size_t)(c + 1) * 8192);
        const float* wb = wbuf + ((c + p0) & 1) * 8192;
#pragma unroll
        for (int ks = 0; ks < 4; ks++) {
            float2 a0[4], a1[4];
            const float* ar = Abase + c * 32 + ks * 8;
#pragma unroll
            for (int mi = 0; mi < 4; mi++) {
                a0[mi] = *(const float2*)(ar + (size_t)(mi * 16) * SAP);
                a1[mi] = *(const float2*)(ar + (size_t)(mi * 16 + 8) * SAP);
            }
            float4 bv[4];
            const float* wp = wb + (ks * 16 + wn * 4) * 128 + lane * 4;
#pragma unroll
            for (int np = 0; np < 4; np++)
                bv[np] = *(const float4*)(wp + np * 128);
#pragma unroll
            for (int np = 0; np < 4; np++) {
                uint32_t b0[2] = {__float_as_uint(bv[np].x), __float_as_uint(bv[np].y)};
                uint32_t b1[2] = {__float_as_uint(bv[np].z), __float_as_uint(bv[np].w)};
#pragma unroll
                for (int mi = 0; mi < 4; mi++) {
                    uint32_t a[4] = {__float_as_uint(a0[mi].x), __float_as_uint(a1[mi].x),
                                     __float_as_uint(a0[mi].y), __float_as_uint(a1[mi].y)};
                    mma8(acc[mi][2 * np], a, b0);
                    mma8(acc[mi][2 * np + 1], a, b1);
                }
            }
        }
    }
    // prefetch next layer's chunk 0 (overlaps caller's epilogue)
    if (nextW)
        stage_chunk(wb_s32 + (uint32_t)(((nch + p0) & 1)) * 32768u, nextW);
}

// ---------------- kernel C: main fused chain, one CTA per (b, i-pair) --------
__global__ void __launch_bounds__(256, 1) k_main(
    const float* __restrict__ gb1, const float* __restrict__ gb2,
    const float* __restrict__ gb3)
{
    extern __shared__ float sm[];
    float* Ap   = sm;
    float* wbuf = sm + OFF_WBUF;
    float* xi_s = sm + OFF_XI;
    float* aib0 = sm + OFF_AIB0;
    float* aib1 = sm + OFF_AIB1;
    float* b2s  = sm + OFF_B2;
    float* b3s  = sm + OFF_B3;

    int tid = threadIdx.x;
    int w = tid >> 5, lane = tid & 31;
    int wm = w >> 2, wn = w & 3;           // warp tile: rows [wm*64,+64), cols [wn*64,+64)
    int g = lane >> 2, cth = lane & 3;
    int b = blockIdx.x >> 5, ip = blockIdx.x & 31;
    int i0 = 2 * ip, i1 = 2 * ip + 1;

    uint32_t wb_s32 = (uint32_t)__cvta_generic_to_shared(wbuf);
    const float* Xb = d_X + (size_t)b * S_ * SA;

    // kick off layer-1 chunk 0 weight load immediately (overlaps prologue + P build)
    stage_chunk(wb_s32, d_W1f);

    // prologue: xi rows, biases
    for (int k = tid; k < 2 * SA; k += 256) {
        int half = k >= SA, kk = k - half * SA;
        xi_s[k] = Xb[(size_t)(half ? i1 : i0) * SA + kk];
    }
    aib0[tid] = d_AI[(size_t)(b * S_ + i0) * H_ + tid] + gb1[tid];
    aib1[tid] = d_AI[(size_t)(b * S_ + i1) * H_ + tid] + gb1[tid];
    b2s[tid] = gb2[tid];
    b3s[tid] = gb3[tid];
    __syncthreads();

    // build P tile into Ap (permuted-k layout): P[r,k] = tf32(x_i[k]*x_j[k])
    // per 8-k group, positions hold k order [0,4,1,5,2,6,3,7]
#pragma unroll 2
    for (int q = 0; q < 18; q++) {
        int e = tid + q * 256;              // 128 rows x 36 groups
        int r = e / 36, grp = e % 36;
        int half = r >> 6, j = r & 63;
        int k0 = grp * 8;
        float4 fa = make_float4(0.f, 0.f, 0.f, 0.f), fb = fa;
        if (k0 < 272) {
            float4 xj = *(const float4*)(Xb + (size_t)j * SA + k0);
            float4 xi = *(const float4*)(xi_s + half * SA + k0);
            fa.x = tf32r(xj.x * xi.x); fa.y = tf32r(xj.y * xi.y);
            fa.z = tf32r(xj.z * xi.z); fa.w = tf32r(xj.w * xi.w);
            if (k0 + 4 < 272) {
                float4 xj2 = *(const float4*)(Xb + (size_t)j * SA + k0 + 4);
                float4 xi2 = *(const float4*)(xi_s + half * SA + k0 + 4);
                fb.x = tf32r(xj2.x * xi2.x); fb.y = tf32r(xj2.y * xi2.y);
                fb.z = tf32r(xj2.z * xi2.z); fb.w = tf32r(xj2.w * xi2.w);
            }
        }
        float* dst = Ap + (size_t)r * SAP + k0;
        *(float4*)(dst)     = make_float4(fa.x, fb.x, fa.y, fb.y);
        *(float4*)(dst + 4) = make_float4(fa.z, fb.z, fa.w, fb.w);
    }
    // visibility: gemm's first wait+__syncthreads

    float acc[4][8][4];
    int pos0 = (cth & 1) * 4 + (cth >> 1);   // permuted slot for col (2*cth)

    // ======== layer 1 ========
    gemm_frag(acc, Ap, wbuf, wb_s32, d_W1f, 9, 0, d_W2f, wm, wn, g, cth);
    __syncthreads();                          // all warps done reading Ap
    {
        const float* AJb = d_AJ + (size_t)(b * S_) * H_;
        const float* aibp = wm ? aib1 : aib0;
#pragma unroll
        for (int mi = 0; mi < 4; mi++) {
            int r = wm * 64 + mi * 16 + g;
            int j0 = r & 63;
            const float* AJ0 = AJb + (size_t)j0 * H_;
            const float* AJ1 = AJb + (size_t)(j0 + 8) * H_;
#pragma unroll
            for (int ni = 0; ni < 8; ni++) {
                int c0 = wn * 64 + ni * 8 + 2 * cth;
                float2 aj0 = *(const float2*)(AJ0 + c0);
                float2 aj1 = *(const float2*)(AJ1 + c0);
                float2 ab  = *(const float2*)(aibp + c0);
                float v00 = tf32r(fmaxf(acc[mi][ni][0] + aj0.x + ab.x, 0.f));
                float v01 = tf32r(fmaxf(acc[mi][ni][1] + aj0.y + ab.y, 0.f));
                float v10 = tf32r(fmaxf(acc[mi][ni][2] + aj1.x + ab.x, 0.f));
                float v11 = tf32r(fmaxf(acc[mi][ni][3] + aj1.y + ab.y, 0.f));
                int base = (wn * 8 + ni) * 8 + pos0;
                Ap[(size_t)r * SAP + base]           = v00;
                Ap[(size_t)r * SAP + base + 2]       = v01;
                Ap[(size_t)(r + 8) * SAP + base]     = v10;
                Ap[(size_t)(r + 8) * SAP + base + 2] = v11;
            }
        }
    }

    // ======== layer 2 ========
    gemm_frag(acc, Ap, wbuf, wb_s32, d_W2f, 8, 1, d_W3f, wm, wn, g, cth);
    __syncthreads();
    {
#pragma unroll
        for (int mi = 0; mi < 4; mi++) {
            int r = wm * 64 + mi * 16 + g;
#pragma unroll
            for (int ni = 0; ni < 8; ni++) {
                int c0 = wn * 64 + ni * 8 + 2 * cth;
                float2 ab = *(const float2*)(b2s + c0);
                float v00 = tf32r(fmaxf(acc[mi][ni][0] + ab.x, 0.f));
                float v01 = tf32r(fmaxf(acc[mi][ni][1] + ab.y, 0.f));
                float v10 = tf32r(fmaxf(acc[mi][ni][2] + ab.x, 0.f));
                float v11 = tf32r(fmaxf(acc[mi][ni][3] + ab.y, 0.f));
                int base = (wn * 8 + ni) * 8 + pos0;
                Ap[(size_t)r * SAP + base]           = v00;
                Ap[(size_t)r * SAP + base + 2]       = v01;
                Ap[(size_t)(r + 8) * SAP + base]     = v10;
                Ap[(size_t)(r + 8) * SAP + base + 2] = v11;
            }
        }
    }

    // ======== layer 3 + row reduction ========
    gemm_frag(acc, Ap, wbuf, wb_s32, d_W3f, 8, 1, (const float*)0, wm, wn, g, cth);
    __syncthreads();
    {
#pragma unroll
        for (int mi = 0; mi < 4; mi++) {
            int r = wm * 64 + mi * 16 + g;
#pragma unroll
            for (int ni = 0; ni < 8; ni++) {
                int c0 = wn * 64 + ni * 8 + 2 * cth;
                float2 ab = *(const float2*)(b3s + c0);
                float v00 = fmaxf(acc[mi][ni][0] + ab.x, 0.f);
                float v01 = fmaxf(acc[mi][ni][1] + ab.y, 0.f);
                float v10 = fmaxf(acc[mi][ni][2] + ab.x, 0.f);
                float v11 = fmaxf(acc[mi][ni][3] + ab.y, 0.f);
                *(float2*)(Ap + (size_t)r * SAP + c0)       = make_float2(v00, v01);
                *(float2*)(Ap + (size_t)(r + 8) * SAP + c0) = make_float2(v10, v11);
            }
        }
        __syncthreads();
        float s0 = 0.f, s1 = 0.f;
#pragma unroll 8
        for (int rr = 0; rr < 64; rr++) {
            s0 += Ap[(size_t)rr * SAP + tid];
            s1 += Ap[(size_t)(64 + rr) * SAP + tid];
        }
        d_PART[(size_t)(b * S_ + i0) * H_ + tid] = s0;
        d_PART[(size_t)(b * S_ + i1) * H_ + tid] = s1;
    }
}

// ---------------- kernel D: reduce over i + final MLP (512 thr, split-K) -----
__global__ void __launch_bounds__(512) k_final(
    const float* __restrict__ fw1, const float* __restrict__ fb1,
    const float* __restrict__ fw2, const float* __restrict__ fb2,
    const float* __restrict__ fw3, const float* __restrict__ fb3,
    float* __restrict__ out)
{
    __shared__ float s0[H_], s1[H_], s2[H_], part[512];
    int b = blockIdx.x;
    int t = threadIdx.x & 255, h = threadIdx.x >> 8;

    const float* P = d_PART + (size_t)b * S_ * H_;
    float s = 0.f;
#pragma unroll 8
    for (int i = h * 32; i < h * 32 + 32; i++) s += P[i * H_ + t];
    part[h * 256 + t] = s;
    __syncthreads();
    if (h == 0) s0[t] = part[t] + part[256 + t];
    __syncthreads();

    // layer 1
    {
        float a0 = 0.f, a1 = 0.f, a2 = 0.f, a3 = 0.f;
        const float* W = fw1 + (size_t)h * 128 * H_;
        const float* si = s0 + h * 128;
#pragma unroll 8
        for (int k = 0; k < 128; k += 4) {
            a0 += si[k]     * W[(size_t)k * H_ + t];
            a1 += si[k + 1] * W[(size_t)(k + 1) * H_ + t];
            a2 += si[k + 2] * W[(size_t)(k + 2) * H_ + t];
            a3 += si[k + 3] * W[(size_t)(k + 3) * H_ + t];
        }
        part[h * 256 + t] = (a0 + a1) + (a2 + a3);
    }
    __syncthreads();
    if (h == 0) s1[t] = fmaxf(part[t] + part[256 + t] + fb1[t], 0.f);
    __syncthreads();

    // layer 2
    {
        float a0 = 0.f, a1 = 0.f, a2 = 0.f, a3 = 0.f;
        const float* W = fw2 + (size_t)h * 128 * H_;
        const float* si = s1 + h * 128;
#pragma unroll 8
        for (int k = 0; k < 128; k += 4) {
            a0 += si[k]     * W[(size_t)k * H_ + t];
            a1 += si[k + 1] * W[(size_t)(k + 1) * H_ + t];
            a2 += si[k + 2] * W[(size_t)(k + 2) * H_ + t];
            a3 += si[k + 3] * W[(size_t)(k + 3) * H_ + t];
        }
        part[h * 256 + t] = (a0 + a1) + (a2 + a3);
    }
    __syncthreads();
    if (h == 0) s2[t] = fmaxf(part[t] + part[256 + t] + fb2[t], 0.f);
    __syncthreads();

    // layer 3
    if (t < OUT_) {
        float a = 0.f;
        const float* si = s2 + h * 128;
        const float* W = fw3 + (size_t)h * 128 * OUT_;
#pragma unroll 8
        for (int k = 0; k < 128; k++) a += si[k] * W[(size_t)k * OUT_ + t];
        part[h * 256 + t] = a;
    }
    __syncthreads();
    if (h == 0 && t < OUT_)
        out[b * OUT_ + t] = part[t] + part[256 + t] + fb3[t];
}

// ---------------- launch ----------------
extern "C" void kernel_launch(void* const* d_in, const int* in_sizes, int n_in,
                              void* d_out, int out_size) {
    const float* sent  = (const float*)d_in[0];
    const float* coord = (const float*)d_in[1];
    const float* gw1   = (const float*)d_in[2];
    const float* gb1   = (const float*)d_in[3];
    const float* gw2   = (const float*)d_in[4];
    const float* gb2   = (const float*)d_in[5];
    const float* gw3   = (const float*)d_in[6];
    const float* gb3   = (const float*)d_in[7];
    const float* fw1   = (const float*)d_in[8];
    const float* fb1   = (const float*)d_in[9];
    const float* fw2   = (const float*)d_in[10];
    const float* fb2   = (const float*)d_in[11];
    const float* fw3   = (const float*)d_in[12];
    const float* fb3   = (const float*)d_in[13];
    float* out = (float*)d_out;

    int nx = B_ * S_ * SA;
    k_build_x<<<(nx + 255) / 256, 256>>>(sent, coord);
    int nw = 9 * 8192 + 2 * 8 * 8192;
    k_roundw<<<(nw + 255) / 256, 256>>>(gw1, gw2, gw3);
    k_precompute<<<(B_ * S_) / 16, 256>>>(gw1);

    size_t smem = (size_t)SMEM_FLOATS * sizeof(float);
    cudaFuncSetAttribute(k_main, cudaFuncAttributeMaxDynamicSharedMemorySize, (int)smem);
    k_main<<<B_ * S_ / 2, 256, smem>>>(gb1, gb2, gb3);

    k_final<<<B_, 512>>>(fw1, fb1, fw2, fb2, fw3, fb3, out);
}

// round 10
// speedup vs baseline: 4.0579x; 1.4013x over previous
#include <cuda_runtime.h>
#include <cuda_fp16.h>
#include <cstdint>
#include <cstddef>

// Problem constants
#define B_   32
#define S_   64
#define KX   258        // D_MODEL + 2
#define SA   272        // d_X row stride (floats)
#define H_   256
#define OUT_ 10

// A/activation tile: 128 rows x 304 halfs. 152 b32/row, 152%32==24 ->
// LDS.64 banks (24g+2tg) conflict-free per 16-lane phase.
#define ROW32 152
#define ROWH  304

// dynamic smem byte offsets
#define OFF_WB    77824     // A tile: 128*304 halfs = 77824 B
#define OFF_XI    110592    // wbuf: 2 x 16384 B
#define OFF_AIB0  112768
#define OFF_AIB1  113792
#define OFF_B2    114816
#define OFF_B3    115840
#define SMEM_BYTES 116864

// ---------------- device scratch (static; no allocation) ----------------
__device__ __align__(16) float d_X[B_ * S_ * SA];
__device__ __align__(16) float d_AJ[B_ * S_ * H_];
__device__ __align__(16) float d_AI[B_ * S_ * H_];
__device__ __align__(16) float d_PART[B_ * S_ * H_];
// weights as fp16 in per-thread MMA fragment order; chunk = 32k x 256n = 8192 halfs
__device__ __align__(16) __half d_W1f[9 * 8192];
__device__ __align__(16) __half d_W2f[8 * 8192];
__device__ __align__(16) __half d_W3f[8 * 8192];

// ---------------- helpers ----------------
__device__ __forceinline__ void mma16(float (&d)[4], const uint32_t (&a)[4],
                                      const uint32_t (&b)[2]) {
    asm volatile(
        "mma.sync.aligned.m16n8k16.row.col.f32.f16.f16.f32 "
        "{%0,%1,%2,%3}, {%4,%5,%6,%7}, {%8,%9}, {%0,%1,%2,%3};"
        : "+f"(d[0]), "+f"(d[1]), "+f"(d[2]), "+f"(d[3])
        : "r"(a[0]), "r"(a[1]), "r"(a[2]), "r"(a[3]), "r"(b[0]), "r"(b[1]));
}
__device__ __forceinline__ void cpasync16(uint32_t s, const void* g) {
    asm volatile("cp.async.cg.shared.global [%0], [%1], 16;" :: "r"(s), "l"(g));
}
__device__ __forceinline__ uint32_t h2u(__half2 h) {
    return *(uint32_t*)&h;
}

// ---------------- kernel A: build X ----------------
__global__ void k_build_x(const float* __restrict__ sent,
                          const float* __restrict__ coord) {
    int idx = blockIdx.x * 256 + threadIdx.x;
    if (idx >= B_ * S_ * SA) return;
    int k  = idx % SA;
    int bs = idx / SA;
    float v = 0.f;
    if (k < 256)      v = sent[bs * 256 + k];
    else if (k < 258) v = coord[bs * 2 + (k - 256)];
    d_X[idx] = v;
}

// ---------------- kernel A2: weights -> fp16 fragment layout ----------------
// chunk element e in [0,8192): off_b32=e>>1, h=e&1; ks=off>>11; rem=off&2047;
//   nb=rem>>6; lane=(rem&63)>>1; j=rem&1; tg=lane&3; g=lane>>2
//   k = c*32 + ks*16 + j*8 + 2*tg + h ;  n = nb*8 + g
__global__ void k_roundw(const float* __restrict__ gw1,
                         const float* __restrict__ gw2,
                         const float* __restrict__ gw3) {
    int idx = blockIdx.x * 256 + threadIdx.x;
    if (idx >= 9 * 8192 + 2 * 8 * 8192) return;
    int layer, e;
    if (idx < 9 * 8192)                    { layer = 1; e = idx; }
    else if (idx < 9 * 8192 + 8 * 8192)    { layer = 2; e = idx - 9 * 8192; }
    else                                   { layer = 3; e = idx - 9 * 8192 - 8 * 8192; }
    int c = e >> 13, f = e & 8191;
    int off = f >> 1, h = f & 1;
    int ks = off >> 11, rem = off & 2047;
    int nb = rem >> 6, l2 = rem & 63;
    int lane = l2 >> 1, j = l2 & 1;
    int tg = lane & 3, g = lane >> 2;
    int k = c * 32 + ks * 16 + j * 8 + 2 * tg + h;
    int n = nb * 8 + g;
    if (layer == 1)
        d_W1f[e] = (k < KX) ? __float2half_rn(gw1[(size_t)(516 + k) * H_ + n])
                            : __float2half_rn(0.f);
    else if (layer == 2)
        d_W2f[e] = __float2half_rn(gw2[(size_t)k * H_ + n]);
    else
        d_W3f[e] = __float2half_rn(gw3[(size_t)k * H_ + n]);
}

// ---------------- kernel B: precompute AJ, AI (fp32) ----------------
__global__ void __launch_bounds__(256) k_precompute(const float* __restrict__ gw1) {
    __shared__ float Xs[16 * SA];
    int r0  = blockIdx.x * 16;
    int tid = threadIdx.x;
    for (int t = tid; t < 16 * SA; t += 256) Xs[t] = d_X[r0 * SA + t];
    __syncthreads();

    float accJ[16], accI[16];
#pragma unroll
    for (int s = 0; s < 16; s++) { accJ[s] = 0.f; accI[s] = 0.f; }

#pragma unroll 2
    for (int k = 0; k < KX; k++) {
        float wj = gw1[k * H_ + tid];
        float wi = gw1[(KX + k) * H_ + tid];
#pragma unroll
        for (int s = 0; s < 16; s++) {
            float xv = Xs[s * SA + k];
            accJ[s] += xv * wj;
            accI[s] += xv * wi;
        }
    }
#pragma unroll
    for (int s = 0; s < 16; s++) {
        d_AJ[(r0 + s) * H_ + tid] = accJ[s];
        d_AI[(r0 + s) * H_ + tid] = accI[s];
    }
}

// ---------------- weight chunk staging: linear 16KB copy ----------------
__device__ __forceinline__ void stage_chunk(uint32_t bdst, const __half* __restrict__ W) {
    int tid = threadIdx.x;
#pragma unroll
    for (int it = 0; it < 4; it++) {
        int seg = tid + it * 256;
        cpasync16(bdst + (uint32_t)seg * 16u, (const char*)W + (size_t)seg * 16);
    }
    asm volatile("cp.async.commit_group;");
}

// ---------------- fp16 fragment GEMM: 128x256, K chunks of 32 ----------------
__device__ __forceinline__ void gemm_frag(
    float (&acc)[4][8][4],
    const uint32_t* __restrict__ Ap32,
    const uint32_t* __restrict__ wbuf, uint32_t wb_s32,
    const __half* __restrict__ W, int nch, int p0,
    const __half* __restrict__ nextW,
    int wm, int wn, int g, int tg)
{
#pragma unroll
    for (int mi = 0; mi < 4; mi++)
#pragma unroll
        for (int ni = 0; ni < 8; ni++)
#pragma unroll
            for (int q = 0; q < 4; q++) acc[mi][ni][q] = 0.f;

    int lane = threadIdx.x & 31;
    const uint32_t* A0 = Ap32 + (size_t)(wm * 64 + g) * ROW32 + 2 * tg;

    for (int c = 0; c < nch; c++) {
        asm volatile("cp.async.wait_group 0;" ::: "memory");
        __syncthreads();
        if (c + 1 < nch)
            stage_chunk(wb_s32 + (uint32_t)(((c + 1 + p0) & 1)) * 16384u,
                        W + (size_t)(c + 1) * 8192);
        const uint32_t* wb = wbuf + ((c + p0) & 1) * 4096;
#pragma unroll
        for (int ks = 0; ks < 2; ks++) {
            uint32_t a[4][4];
            const uint32_t* ar = A0 + c * 16 + ks * 8;
#pragma unroll
            for (int mi = 0; mi < 4; mi++) {
                uint2 L0 = *(const uint2*)(ar + (size_t)(mi * 16) * ROW32);
                uint2 L1 = *(const uint2*)(ar + (size_t)(mi * 16 + 8) * ROW32);
                a[mi][0] = L0.x; a[mi][1] = L1.x; a[mi][2] = L0.y; a[mi][3] = L1.y;
            }
            const uint32_t* wp = wb + ks * 2048 + (wn * 8) * 64 + lane * 2;
#pragma unroll
            for (int ni = 0; ni < 8; ni++) {
                uint2 bb = *(const uint2*)(wp + ni * 64);
                uint32_t b[2] = {bb.x, bb.y};
                mma16(acc[0][ni], a[0], b);
                mma16(acc[1][ni], a[1], b);
                mma16(acc[2][ni], a[2], b);
                mma16(acc[3][ni], a[3], b);
            }
        }
    }
    if (nextW)
        stage_chunk(wb_s32 + (uint32_t)(((nch + p0) & 1)) * 16384u, nextW);
}

// ---------------- kernel C: main fused chain, one CTA per (b, i-pair) --------
__global__ void __launch_bounds__(256, 1) k_main(
    const float* __restrict__ gb1, const float* __restrict__ gb2,
    const float* __restrict__ gb3)
{
    extern __shared__ char smc[];
    uint32_t* Ap32 = (uint32_t*)smc;
    uint32_t* wbuf = (uint32_t*)(smc + OFF_WB);
    float* xi_s = (float*)(smc + OFF_XI);
    float* aib0 = (float*)(smc + OFF_AIB0);
    float* aib1 = (float*)(smc + OFF_AIB1);
    float* b2s  = (float*)(smc + OFF_B2);
    float* b3s  = (float*)(smc + OFF_B3);

    int tid = threadIdx.x;
    int w = tid >> 5, lane = tid & 31;
    int wm = w >> 2, wn = w & 3;           // warp tile rows [wm*64,+64) cols [wn*64,+64)
    int g = lane >> 2, tg = lane & 3;
    int b = blockIdx.x >> 5, ip = blockIdx.x & 31;
    int i0 = 2 * ip, i1 = 2 * ip + 1;

    uint32_t wb_s32 = (uint32_t)__cvta_generic_to_shared(wbuf);
    const float* Xb = d_X + (size_t)b * S_ * SA;

    // kick layer-1 chunk 0 weight load (overlaps prologue + P build)
    stage_chunk(wb_s32, d_W1f);

    // prologue: xi rows, biases (fp32)
    for (int k = tid; k < 2 * SA; k += 256) {
        int half_ = k >= SA, kk = k - half_ * SA;
        xi_s[k] = Xb[(size_t)(half_ ? i1 : i0) * SA + kk];
    }
    aib0[tid] = d_AI[(size_t)(b * S_ + i0) * H_ + tid] + gb1[tid];
    aib1[tid] = d_AI[(size_t)(b * S_ + i1) * H_ + tid] + gb1[tid];
    b2s[tid] = gb2[tid];
    b3s[tid] = gb3[tid];
    __syncthreads();

    // build P tile (half, k-permuted fragment layout):
    // per 16-k group, b32 slot p holds k = 2*(p>>1)+8*(p&1), +1
#pragma unroll 1
    for (int q = 0; q < 9; q++) {
        int e = tid + q * 256;              // 128 rows x 18 groups
        int r = e / 18, gp = e % 18;
        int half_ = r >> 6, j = r & 63;
        uint4 u0 = make_uint4(0u, 0u, 0u, 0u), u1 = u0;
        if (gp < 17) {
            const float* xj = Xb + (size_t)j * SA + gp * 16;
            const float* xv = xi_s + half_ * SA + gp * 16;
            float p[16];
#pragma unroll
            for (int t = 0; t < 4; t++) {
                float4 a = *(const float4*)(xj + t * 4);
                float4 c = *(const float4*)(xv + t * 4);
                p[t*4+0] = a.x * c.x; p[t*4+1] = a.y * c.y;
                p[t*4+2] = a.z * c.z; p[t*4+3] = a.w * c.w;
            }
            uint32_t wv[8];
#pragma unroll
            for (int pp = 0; pp < 8; pp++) {
                int kk = 2 * (pp >> 1) + 8 * (pp & 1);
                wv[pp] = h2u(__floats2half2_rn(p[kk], p[kk + 1]));
            }
            u0 = make_uint4(wv[0], wv[1], wv[2], wv[3]);
            u1 = make_uint4(wv[4], wv[5], wv[6], wv[7]);
        }
        uint4* dst = (uint4*)(Ap32 + (size_t)r * ROW32 + gp * 8);
        dst[0] = u0; dst[1] = u1;
    }
    // visibility: gemm's first wait + __syncthreads

    float acc[4][8][4];

    // ======== layer 1 ========
    gemm_frag(acc, Ap32, wbuf, wb_s32, d_W1f, 9, 0, d_W2f, wm, wn, g, tg);
    __syncthreads();                      // all warps done reading Ap
    {
        const float* AJb = d_AJ + (size_t)(b * S_) * H_;
        const float* aibp = wm ? aib1 : aib0;
#pragma unroll
        for (int mi = 0; mi < 4; mi++) {
            int r = wm * 64 + mi * 16 + g;
            int j0 = r & 63;
            const float* AJ0 = AJb + (size_t)j0 * H_;
            const float* AJ1 = AJb + (size_t)(j0 + 8) * H_;
#pragma unroll
            for (int ni = 0; ni < 8; ni++) {
                int c0 = wn * 64 + ni * 8 + 2 * tg;
                float2 aj0 = *(const float2*)(AJ0 + c0);
                float2 aj1 = *(const float2*)(AJ1 + c0);
                float2 ab  = *(const float2*)(aibp + c0);
                float v00 = fmaxf(acc[mi][ni][0] + aj0.x + ab.x, 0.f);
                float v01 = fmaxf(acc[mi][ni][1] + aj0.y + ab.y, 0.f);
                float v10 = fmaxf(acc[mi][ni][2] + aj1.x + ab.x, 0.f);
                float v11 = fmaxf(acc[mi][ni][3] + aj1.y + ab.y, 0.f);
                uint32_t boff = (uint32_t)((wn * 4 + (ni >> 1)) * 8 + 2 * tg + (ni & 1));
                Ap32[(size_t)r * ROW32 + boff]       = h2u(__floats2half2_rn(v00, v01));
                Ap32[(size_t)(r + 8) * ROW32 + boff] = h2u(__floats2half2_rn(v10, v11));
            }
        }
    }

    // ======== layer 2 ========
    gemm_frag(acc, Ap32, wbuf, wb_s32, d_W2f, 8, 1, d_W3f, wm, wn, g, tg);
    __syncthreads();
    {
#pragma unroll
        for (int mi = 0; mi < 4; mi++) {
            int r = wm * 64 + mi * 16 + g;
#pragma unroll
            for (int ni = 0; ni < 8; ni++) {
                int c0 = wn * 64 + ni * 8 + 2 * tg;
                float2 ab = *(const float2*)(b2s + c0);
                float v00 = fmaxf(acc[mi][ni][0] + ab.x, 0.f);
                float v01 = fmaxf(acc[mi][ni][1] + ab.y, 0.f);
                float v10 = fmaxf(acc[mi][ni][2] + ab.x, 0.f);
                float v11 = fmaxf(acc[mi][ni][3] + ab.y, 0.f);
                uint32_t boff = (uint32_t)((wn * 4 + (ni >> 1)) * 8 + 2 * tg + (ni & 1));
                Ap32[(size_t)r * ROW32 + boff]       = h2u(__floats2half2_rn(v00, v01));
                Ap32[(size_t)(r + 8) * ROW32 + boff] = h2u(__floats2half2_rn(v10, v11));
            }
        }
    }

    // ======== layer 3 + row reduction ========
    gemm_frag(acc, Ap32, wbuf, wb_s32, d_W3f, 8, 1, (const __half*)0, wm, wn, g, tg);
    __syncthreads();
    {
#pragma unroll
        for (int mi = 0; mi < 4; mi++) {
            int r = wm * 64 + mi * 16 + g;
#pragma unroll
            for (int ni = 0; ni < 8; ni++) {
                int c0 = wn * 64 + ni * 8 + 2 * tg;
                float2 ab = *(const float2*)(b3s + c0);
                float v00 = fmaxf(acc[mi][ni][0] + ab.x, 0.f);
                float v01 = fmaxf(acc[mi][ni][1] + ab.y, 0.f);
                float v10 = fmaxf(acc[mi][ni][2] + ab.x, 0.f);
                float v11 = fmaxf(acc[mi][ni][3] + ab.y, 0.f);
                // plain layout for the reduction
                Ap32[(size_t)r * ROW32 + (c0 >> 1)]       = h2u(__floats2half2_rn(v00, v01));
                Ap32[(size_t)(r + 8) * ROW32 + (c0 >> 1)] = h2u(__floats2half2_rn(v10, v11));
            }
        }
        __syncthreads();
        const __half* Aph = (const __half*)smc;
        float s0 = 0.f, s1 = 0.f;
#pragma unroll 8
        for (int rr = 0; rr < 64; rr++) {
            s0 += __half2float(Aph[(size_t)rr * ROWH + tid]);
            s1 += __half2float(Aph[(size_t)(64 + rr) * ROWH + tid]);
        }
        d_PART[(size_t)(b * S_ + i0) * H_ + tid] = s0;
        d_PART[(size_t)(b * S_ + i1) * H_ + tid] = s1;
    }
}

// ---------------- kernel D: reduce over i + final MLP (512 thr, split-K) -----
__global__ void __launch_bounds__(512) k_final(
    const float* __restrict__ fw1, const float* __restrict__ fb1,
    const float* __restrict__ fw2, const float* __restrict__ fb2,
    const float* __restrict__ fw3, const float* __restrict__ fb3,
    float* __restrict__ out)
{
    __shared__ float s0[H_], s1[H_], s2[H_], part[512];
    int b = blockIdx.x;
    int t = threadIdx.x & 255, h = threadIdx.x >> 8;

    const float* P = d_PART + (size_t)b * S_ * H_;
    float s = 0.f;
#pragma unroll 8
    for (int i = h * 32; i < h * 32 + 32; i++) s += P[i * H_ + t];
    part[h * 256 + t] = s;
    __syncthreads();
    if (h == 0) s0[t] = part[t] + part[256 + t];
    __syncthreads();

    // layer 1
    {
        float a0 = 0.f, a1 = 0.f, a2 = 0.f, a3 = 0.f;
        const float* W = fw1 + (size_t)h * 128 * H_;
        const float* si = s0 + h * 128;
#pragma unroll 8
        for (int k = 0; k < 128; k += 4) {
            a0 += si[k]     * W[(size_t)k * H_ + t];
            a1 += si[k + 1] * W[(size_t)(k + 1) * H_ + t];
            a2 += si[k + 2] * W[(size_t)(k + 2) * H_ + t];
            a3 += si[k + 3] * W[(size_t)(k + 3) * H_ + t];
        }
        part[h * 256 + t] = (a0 + a1) + (a2 + a3);
    }
    __syncthreads();
    if (h == 0) s1[t] = fmaxf(part[t] + part[256 + t] + fb1[t], 0.f);
    __syncthreads();

    // layer 2
    {
        float a0 = 0.f, a1 = 0.f, a2 = 0.f, a3 = 0.f;
        const float* W = fw2 + (size_t)h * 128 * H_;
        const float* si = s1 + h * 128;
#pragma unroll 8
        for (int k = 0; k < 128; k += 4) {
            a0 += si[k]     * W[(size_t)k * H_ + t];
            a1 += si[k + 1] * W[(size_t)(k + 1) * H_ + t];
            a2 += si[k + 2] * W[(size_t)(k + 2) * H_ + t];
            a3 += si[k + 3] * W[(size_t)(k + 3) * H_ + t];
        }
        part[h * 256 + t] = (a0 + a1) + (a2 + a3);
    }
    __syncthreads();
    if (h == 0) s2[t] = fmaxf(part[t] + part[256 + t] + fb2[t], 0.f);
    __syncthreads();

    // layer 3
    if (t < OUT_) {
        float a = 0.f;
        const float* si = s2 + h * 128;
        const float* W = fw3 + (size_t)h * 128 * OUT_;
#pragma unroll 8
        for (int k = 0; k < 128; k++) a += si[k] * W[(size_t)k * OUT_ + t];
        part[h * 256 + t] = a;
    }
    __syncthreads();
    if (h == 0 && t < OUT_)
        out[b * OUT_ + t] = part[t] + part[256 + t] + fb3[t];
}

// ---------------- launch ----------------
extern "C" void kernel_launch(void* const* d_in, const int* in_sizes, int n_in,
                              void* d_out, int out_size) {
    const float* sent  = (const float*)d_in[0];
    const float* coord = (const float*)d_in[1];
    const float* gw1   = (const float*)d_in[2];
    const float* gb1   = (const float*)d_in[3];
    const float* gw2   = (const float*)d_in[4];
    const float* gb2   = (const float*)d_in[5];
    const float* gw3   = (const float*)d_in[6];
    const float* gb3   = (const float*)d_in[7];
    const float* fw1   = (const float*)d_in[8];
    const float* fb1   = (const float*)d_in[9];
    const float* fw2   = (const float*)d_in[10];
    const float* fb2   = (const float*)d_in[11];
    const float* fw3   = (const float*)d_in[12];
    const float* fb3   = (const float*)d_in[13];
    float* out = (float*)d_out;

    int nx = B_ * S_ * SA;
    k_build_x<<<(nx + 255) / 256, 256>>>(sent, coord);
    int nw = 9 * 8192 + 2 * 8 * 8192;
    k_roundw<<<(nw + 255) / 256, 256>>>(gw1, gw2, gw3);
    k_precompute<<<(B_ * S_) / 16, 256>>>(gw1);

    cudaFuncSetAttribute(k_main, cudaFuncAttributeMaxDynamicSharedMemorySize,
                         SMEM_BYTES);
    k_main<<<B_ * S_ / 2, 256, SMEM_BYTES>>>(gb1, gb2, gb3);

    k_final<<<B_, 512>>>(fw1, fb1, fw2, fb2, fw3, fb3, out);
}

// round 11
// speedup vs baseline: 4.0817x; 1.0059x over previous
#include <cuda_runtime.h>
#include <cuda_fp16.h>
#include <cstdint>
#include <cstddef>

// Problem constants
#define B_   32
#define S_   64
#define KX   258        // D_MODEL + 2
#define SA   272        // d_X row stride (floats)
#define H_   256
#define OUT_ 10

// A/activation tile: 128 rows x 304 halfs (152 b32/row; 152%32==24 ->
// LDS.64 banks 24g+2tg conflict-free per 16-lane phase)
#define ROW32 152
#define ROWH  304

// dynamic smem byte offsets
#define OFF_WB    77824     // A tile: 128*304 halfs = 77824 B
#define OFF_XI    110592    // wbuf: 2 x 16384 B
#define OFF_AIB0  112768
#define OFF_AIB1  113792
#define OFF_B2    114816
#define OFF_B3    115840
#define SMEM_BYTES 116864

#define NW_ROUND (9 * 8192 + 2 * 8 * 8192)   // 204800 fragment elements

// ---------------- device scratch (static; no allocation) ----------------
__device__ __align__(16) float d_X[B_ * S_ * SA];
__device__ __align__(16) float d_AJ[B_ * S_ * H_];
__device__ __align__(16) float d_AI[B_ * S_ * H_];
__device__ __align__(16) float d_PART[B_ * S_ * H_];
// weights fp16 in per-thread MMA fragment order; chunk = 32k x 256n = 8192 halfs
__device__ __align__(16) __half d_W1f[9 * 8192];
__device__ __align__(16) __half d_W2f[8 * 8192];
__device__ __align__(16) __half d_W3f[8 * 8192];

// ---------------- helpers ----------------
__device__ __forceinline__ void mma16(float (&d)[4], const uint32_t (&a)[4],
                                      const uint32_t (&b)[2]) {
    asm volatile(
        "mma.sync.aligned.m16n8k16.row.col.f32.f16.f16.f32 "
        "{%0,%1,%2,%3}, {%4,%5,%6,%7}, {%8,%9}, {%0,%1,%2,%3};"
        : "+f"(d[0]), "+f"(d[1]), "+f"(d[2]), "+f"(d[3])
        : "r"(a[0]), "r"(a[1]), "r"(a[2]), "r"(a[3]), "r"(b[0]), "r"(b[1]));
}
__device__ __forceinline__ void cpasync16(uint32_t s, const void* g) {
    asm volatile("cp.async.cg.shared.global [%0], [%1], 16;" :: "r"(s), "l"(g));
}
__device__ __forceinline__ uint32_t h2u(__half2 h) {
    return *(uint32_t*)&h;
}

// ---------------- kernel P: fused prep (build X + AJ/AI + weight fragments) --
// blocks [0,128): build X rows + precompute AJ/AI
// blocks [128, 128+800): rearrange weights into fp16 fragment order
__global__ void __launch_bounds__(256) k_prep(
    const float* __restrict__ sent, const float* __restrict__ coord,
    const float* __restrict__ gw1, const float* __restrict__ gw2,
    const float* __restrict__ gw3)
{
    int blk = blockIdx.x, tid = threadIdx.x;
    if (blk < 128) {
        __shared__ float Xs[16 * SA];
        int r0 = blk * 16;
        for (int t = tid; t < 16 * SA; t += 256) {
            int sl = t / SA, k = t % SA;
            int bs = r0 + sl;
            float v = 0.f;
            if (k < 256)      v = sent[(size_t)bs * 256 + k];
            else if (k < 258) v = coord[(size_t)bs * 2 + (k - 256)];
            Xs[t] = v;
            d_X[(size_t)r0 * SA + t] = v;
        }
        __syncthreads();

        float accJ[16], accI[16];
#pragma unroll
        for (int s = 0; s < 16; s++) { accJ[s] = 0.f; accI[s] = 0.f; }
#pragma unroll 2
        for (int k = 0; k < KX; k++) {
            float wj = gw1[k * H_ + tid];
            float wi = gw1[(KX + k) * H_ + tid];
#pragma unroll
            for (int s = 0; s < 16; s++) {
                float xv = Xs[s * SA + k];
                accJ[s] += xv * wj;
                accI[s] += xv * wi;
            }
        }
#pragma unroll
        for (int s = 0; s < 16; s++) {
            d_AJ[(r0 + s) * H_ + tid] = accJ[s];
            d_AI[(r0 + s) * H_ + tid] = accI[s];
        }
    } else {
        int idx = (blk - 128) * 256 + tid;
        if (idx >= NW_ROUND) return;
        int layer, e;
        if (idx < 9 * 8192)                 { layer = 1; e = idx; }
        else if (idx < 9 * 8192 + 8 * 8192) { layer = 2; e = idx - 9 * 8192; }
        else                                { layer = 3; e = idx - 9 * 8192 - 8 * 8192; }
        int c = e >> 13, f = e & 8191;
        int off = f >> 1, h = f & 1;
        int ks = off >> 11, rem = off & 2047;
        int nb = rem >> 6, l2 = rem & 63;
        int lane = l2 >> 1, j = l2 & 1;
        int tg = lane & 3, g = lane >> 2;
        int k = c * 32 + ks * 16 + j * 8 + 2 * tg + h;
        int n = nb * 8 + g;
        if (layer == 1)
            d_W1f[e] = (k < KX) ? __float2half_rn(gw1[(size_t)(516 + k) * H_ + n])
                                : __float2half_rn(0.f);
        else if (layer == 2)
            d_W2f[e] = __float2half_rn(gw2[(size_t)k * H_ + n]);
        else
            d_W3f[e] = __float2half_rn(gw3[(size_t)k * H_ + n]);
    }
}

// ---------------- weight chunk staging: linear 16KB copy (512 thr) -----------
__device__ __forceinline__ void stage_chunk(uint32_t bdst, const __half* __restrict__ W) {
    int tid = threadIdx.x;
#pragma unroll
    for (int it = 0; it < 2; it++) {
        int seg = tid + it * 512;
        cpasync16(bdst + (uint32_t)seg * 16u, (const char*)W + (size_t)seg * 16);
    }
    asm volatile("cp.async.commit_group;");
}

// ---------------- fp16 fragment GEMM: 128x256, 16 warps, warp tile 32x64 -----
__device__ __forceinline__ void gemm_frag(
    float (&acc)[2][8][4],
    const uint32_t* __restrict__ Ap32,
    const uint32_t* __restrict__ wbuf, uint32_t wb_s32,
    const __half* __restrict__ W, int nch, int p0,
    const __half* __restrict__ nextW,
    int wm, int wn, int g, int tg)
{
#pragma unroll
    for (int mi = 0; mi < 2; mi++)
#pragma unroll
        for (int ni = 0; ni < 8; ni++)
#pragma unroll
            for (int q = 0; q < 4; q++) acc[mi][ni][q] = 0.f;

    int lane = threadIdx.x & 31;
    const uint32_t* A0 = Ap32 + (size_t)(wm * 32 + g) * ROW32 + 2 * tg;

    for (int c = 0; c < nch; c++) {
        asm volatile("cp.async.wait_group 0;" ::: "memory");
        __syncthreads();
        if (c + 1 < nch)
            stage_chunk(wb_s32 + (uint32_t)(((c + 1 + p0) & 1)) * 16384u,
                        W + (size_t)(c + 1) * 8192);
        const uint32_t* wb = wbuf + ((c + p0) & 1) * 4096;
#pragma unroll
        for (int ks = 0; ks < 2; ks++) {
            uint32_t a[2][4];
            const uint32_t* ar = A0 + c * 16 + ks * 8;
#pragma unroll
            for (int mi = 0; mi < 2; mi++) {
                uint2 L0 = *(const uint2*)(ar + (size_t)(mi * 16) * ROW32);
                uint2 L1 = *(const uint2*)(ar + (size_t)(mi * 16 + 8) * ROW32);
                a[mi][0] = L0.x; a[mi][1] = L1.x; a[mi][2] = L0.y; a[mi][3] = L1.y;
            }
            const uint32_t* wp = wb + ks * 2048 + (wn * 8) * 64 + lane * 2;
#pragma unroll
            for (int ni = 0; ni < 8; ni++) {
                uint2 bb = *(const uint2*)(wp + ni * 64);
                uint32_t b[2] = {bb.x, bb.y};
                mma16(acc[0][ni], a[0], b);
                mma16(acc[1][ni], a[1], b);
            }
        }
    }
    if (nextW)
        stage_chunk(wb_s32 + (uint32_t)(((nch + p0) & 1)) * 16384u, nextW);
}

// ---------------- kernel C: main fused chain, 512 thr, one CTA per (b,ipair) -
__global__ void __launch_bounds__(512, 1) k_main(
    const float* __restrict__ gb1, const float* __restrict__ gb2,
    const float* __restrict__ gb3)
{
    extern __shared__ char smc[];
    uint32_t* Ap32 = (uint32_t*)smc;
    uint32_t* wbuf = (uint32_t*)(smc + OFF_WB);
    float* xi_s = (float*)(smc + OFF_XI);
    float* aib0 = (float*)(smc + OFF_AIB0);
    float* aib1 = (float*)(smc + OFF_AIB1);
    float* b2s  = (float*)(smc + OFF_B2);
    float* b3s  = (float*)(smc + OFF_B3);

    int tid = threadIdx.x;
    int w = tid >> 5, lane = tid & 31;
    int wm = w >> 2, wn = w & 3;          // warp tile: rows [wm*32,+32), cols [wn*64,+64)
    int g = lane >> 2, tg = lane & 3;
    int b = blockIdx.x >> 5, ip = blockIdx.x & 31;
    int i0 = 2 * ip, i1 = 2 * ip + 1;

    uint32_t wb_s32 = (uint32_t)__cvta_generic_to_shared(wbuf);
    const float* Xb = d_X + (size_t)b * S_ * SA;

    // kick layer-1 chunk 0 weight load (overlaps prologue + P build)
    stage_chunk(wb_s32, d_W1f);

    // prologue: xi rows + biases
    for (int k = tid; k < 2 * SA; k += 512) {
        int half_ = k >= SA, kk = k - half_ * SA;
        xi_s[k] = Xb[(size_t)(half_ ? i1 : i0) * SA + kk];
    }
    if (tid < 256) {
        aib0[tid] = d_AI[(size_t)(b * S_ + i0) * H_ + tid] + gb1[tid];
        aib1[tid] = d_AI[(size_t)(b * S_ + i1) * H_ + tid] + gb1[tid];
        b2s[tid] = gb2[tid];
        b3s[tid] = gb3[tid];
    }
    __syncthreads();

    // build P tile (half, k-permuted fragment layout)
#pragma unroll 1
    for (int q = 0; q < 5; q++) {
        int e = tid + q * 512;              // 128 rows x 18 groups = 2304
        if (e >= 2304) break;
        int r = e / 18, gp = e % 18;
        int half_ = r >> 6, j = r & 63;
        uint4 u0 = make_uint4(0u, 0u, 0u, 0u), u1 = u0;
        if (gp < 17) {
            const float* xj = Xb + (size_t)j * SA + gp * 16;
            const float* xv = xi_s + half_ * SA + gp * 16;
            float p[16];
#pragma unroll
            for (int t = 0; t < 4; t++) {
                float4 a = *(const float4*)(xj + t * 4);
                float4 c = *(const float4*)(xv + t * 4);
                p[t*4+0] = a.x * c.x; p[t*4+1] = a.y * c.y;
                p[t*4+2] = a.z * c.z; p[t*4+3] = a.w * c.w;
            }
            uint32_t wv[8];
#pragma unroll
            for (int pp = 0; pp < 8; pp++) {
                int kk = 2 * (pp >> 1) + 8 * (pp & 1);
                wv[pp] = h2u(__floats2half2_rn(p[kk], p[kk + 1]));
            }
            u0 = make_uint4(wv[0], wv[1], wv[2], wv[3]);
            u1 = make_uint4(wv[4], wv[5], wv[6], wv[7]);
        }
        uint4* dst = (uint4*)(Ap32 + (size_t)r * ROW32 + gp * 8);
        dst[0] = u0; dst[1] = u1;
    }
    // visibility: gemm's first wait + __syncthreads

    float acc[2][8][4];

    // ======== layer 1 ========
    gemm_frag(acc, Ap32, wbuf, wb_s32, d_W1f, 9, 0, d_W2f, wm, wn, g, tg);
    __syncthreads();                      // all warps done reading Ap
    {
        const float* AJb = d_AJ + (size_t)(b * S_) * H_;
        const float* aibp = (wm >= 2) ? aib1 : aib0;
#pragma unroll
        for (int mi = 0; mi < 2; mi++) {
            int r = wm * 32 + mi * 16 + g;
            int j0 = r & 63;
            const float* AJ0 = AJb + (size_t)j0 * H_;
            const float* AJ1 = AJb + (size_t)(j0 + 8) * H_;
#pragma unroll
            for (int ni = 0; ni < 8; ni++) {
                int c0 = wn * 64 + ni * 8 + 2 * tg;
                float2 aj0 = *(const float2*)(AJ0 + c0);
                float2 aj1 = *(const float2*)(AJ1 + c0);
                float2 ab  = *(const float2*)(aibp + c0);
                float v00 = fmaxf(acc[mi][ni][0] + aj0.x + ab.x, 0.f);
                float v01 = fmaxf(acc[mi][ni][1] + aj0.y + ab.y, 0.f);
                float v10 = fmaxf(acc[mi][ni][2] + aj1.x + ab.x, 0.f);
                float v11 = fmaxf(acc[mi][ni][3] + aj1.y + ab.y, 0.f);
                uint32_t boff = (uint32_t)((wn * 4 + (ni >> 1)) * 8 + 2 * tg + (ni & 1));
                Ap32[(size_t)r * ROW32 + boff]       = h2u(__floats2half2_rn(v00, v01));
                Ap32[(size_t)(r + 8) * ROW32 + boff] = h2u(__floats2half2_rn(v10, v11));
            }
        }
    }

    // ======== layer 2 ========
    gemm_frag(acc, Ap32, wbuf, wb_s32, d_W2f, 8, 1, d_W3f, wm, wn, g, tg);
    __syncthreads();
    {
#pragma unroll
        for (int mi = 0; mi < 2; mi++) {
            int r = wm * 32 + mi * 16 + g;
#pragma unroll
            for (int ni = 0; ni < 8; ni++) {
                int c0 = wn * 64 + ni * 8 + 2 * tg;
                float2 ab = *(const float2*)(b2s + c0);
                float v00 = fmaxf(acc[mi][ni][0] + ab.x, 0.f);
                float v01 = fmaxf(acc[mi][ni][1] + ab.y, 0.f);
                float v10 = fmaxf(acc[mi][ni][2] + ab.x, 0.f);
                float v11 = fmaxf(acc[mi][ni][3] + ab.y, 0.f);
                uint32_t boff = (uint32_t)((wn * 4 + (ni >> 1)) * 8 + 2 * tg + (ni & 1));
                Ap32[(size_t)r * ROW32 + boff]       = h2u(__floats2half2_rn(v00, v01));
                Ap32[(size_t)(r + 8) * ROW32 + boff] = h2u(__floats2half2_rn(v10, v11));
            }
        }
    }

    // ======== layer 3 + row reduction ========
    gemm_frag(acc, Ap32, wbuf, wb_s32, d_W3f, 8, 1, (const __half*)0, wm, wn, g, tg);
    __syncthreads();
    {
#pragma unroll
        for (int mi = 0; mi < 2; mi++) {
            int r = wm * 32 + mi * 16 + g;
#pragma unroll
            for (int ni = 0; ni < 8; ni++) {
                int c0 = wn * 64 + ni * 8 + 2 * tg;
                float2 ab = *(const float2*)(b3s + c0);
                float v00 = fmaxf(acc[mi][ni][0] + ab.x, 0.f);
                float v01 = fmaxf(acc[mi][ni][1] + ab.y, 0.f);
                float v10 = fmaxf(acc[mi][ni][2] + ab.x, 0.f);
                float v11 = fmaxf(acc[mi][ni][3] + ab.y, 0.f);
                // plain layout for the reduction
                Ap32[(size_t)r * ROW32 + (c0 >> 1)]       = h2u(__floats2half2_rn(v00, v01));
                Ap32[(size_t)(r + 8) * ROW32 + (c0 >> 1)] = h2u(__floats2half2_rn(v10, v11));
            }
        }
        __syncthreads();
        const __half* Aph = (const __half*)smc;
        int t = tid & 255, h = tid >> 8;    // h=0 -> rows 0..63 (i0); h=1 -> i1
        float s = 0.f;
#pragma unroll 8
        for (int rr = 0; rr < 64; rr++)
            s += __half2float(Aph[(size_t)(h * 64 + rr) * ROWH + t]);
        d_PART[(size_t)(b * S_ + (h ? i1 : i0)) * H_ + t] = s;
    }
}

// ---------------- kernel D: reduce over i + final MLP (512 thr, split-K) -----
__global__ void __launch_bounds__(512) k_final(
    const float* __restrict__ fw1, const float* __restrict__ fb1,
    const float* __restrict__ fw2, const float* __restrict__ fb2,
    const float* __restrict__ fw3, const float* __restrict__ fb3,
    float* __restrict__ out)
{
    __shared__ float s0[H_], s1[H_], s2[H_], part[512];
    int b = blockIdx.x;
    int t = threadIdx.x & 255, h = threadIdx.x >> 8;

    const float* P = d_PART + (size_t)b * S_ * H_;
    float s = 0.f;
#pragma unroll 8
    for (int i = h * 32; i < h * 32 + 32; i++) s += P[i * H_ + t];
    part[h * 256 + t] = s;
    __syncthreads();
    if (h == 0) s0[t] = part[t] + part[256 + t];
    __syncthreads();

    // layer 1
    {
        float a0 = 0.f, a1 = 0.f, a2 = 0.f, a3 = 0.f;
        const float* W = fw1 + (size_t)h * 128 * H_;
        const float* si = s0 + h * 128;
#pragma unroll 8
        for (int k = 0; k < 128; k += 4) {
            a0 += si[k]     * W[(size_t)k * H_ + t];
            a1 += si[k + 1] * W[(size_t)(k + 1) * H_ + t];
            a2 += si[k + 2] * W[(size_t)(k + 2) * H_ + t];
            a3 += si[k + 3] * W[(size_t)(k + 3) * H_ + t];
        }
        part[h * 256 + t] = (a0 + a1) + (a2 + a3);
    }
    __syncthreads();
    if (h == 0) s1[t] = fmaxf(part[t] + part[256 + t] + fb1[t], 0.f);
    __syncthreads();

    // layer 2
    {
        float a0 = 0.f, a1 = 0.f, a2 = 0.f, a3 = 0.f;
        const float* W = fw2 + (size_t)h * 128 * H_;
        const float* si = s1 + h * 128;
#pragma unroll 8
        for (int k = 0; k < 128; k += 4) {
            a0 += si[k]     * W[(size_t)k * H_ + t];
            a1 += si[k + 1] * W[(size_t)(k + 1) * H_ + t];
            a2 += si[k + 2] * W[(size_t)(k + 2) * H_ + t];
            a3 += si[k + 3] * W[(size_t)(k + 3) * H_ + t];
        }
        part[h * 256 + t] = (a0 + a1) + (a2 + a3);
    }
    __syncthreads();
    if (h == 0) s2[t] = fmaxf(part[t] + part[256 + t] + fb2[t], 0.f);
    __syncthreads();

    // layer 3
    if (t < OUT_) {
        float a = 0.f;
        const float* si = s2 + h * 128;
        const float* W = fw3 + (size_t)h * 128 * OUT_;
#pragma unroll 8
        for (int k = 0; k < 128; k++) a += si[k] * W[(size_t)k * OUT_ + t];
        part[h * 256 + t] = a;
    }
    __syncthreads();
    if (h == 0 && t < OUT_)
        out[b * OUT_ + t] = part[t] + part[256 + t] + fb3[t];
}

// ---------------- launch ----------------
extern "C" void kernel_launch(void* const* d_in, const int* in_sizes, int n_in,
                              void* d_out, int out_size) {
    const float* sent  = (const float*)d_in[0];
    const float* coord = (const float*)d_in[1];
    const float* gw1   = (const float*)d_in[2];
    const float* gb1   = (const float*)d_in[3];
    const float* gw2   = (const float*)d_in[4];
    const float* gb2   = (const float*)d_in[5];
    const float* gw3   = (const float*)d_in[6];
    const float* gb3   = (const float*)d_in[7];
    const float* fw1   = (const float*)d_in[8];
    const float* fb1   = (const float*)d_in[9];
    const float* fw2   = (const float*)d_in[10];
    const float* fb2   = (const float*)d_in[11];
    const float* fw3   = (const float*)d_in[12];
    const float* fb3   = (const float*)d_in[13];
    float* out = (float*)d_out;

    int nblk = 128 + (NW_ROUND + 255) / 256;
    k_prep<<<nblk, 256>>>(sent, coord, gw1, gw2, gw3);

    cudaFuncSetAttribute(k_main, cudaFuncAttributeMaxDynamicSharedMemorySize,
                         SMEM_BYTES);
    k_main<<<B_ * S_ / 2, 512, SMEM_BYTES>>>(gb1, gb2, gb3);

    k_final<<<B_, 512>>>(fw1, fb1, fw2, fb2, fw3, fb3, out);
}

// round 12
// speedup vs baseline: 4.4622x; 1.0932x over previous
#include <cuda_runtime.h>
#include <cuda_fp16.h>
#include <cstdint>
#include <cstddef>

// Problem constants
#define B_   32
#define S_   64
#define KX   258        // D_MODEL + 2
#define SA   272        // d_X row stride (floats)
#define H_   256
#define OUT_ 10

// A/activation tile: 128 rows x 304 halfs (152 b32/row)
#define ROW32 152
#define ROWH  304

// dynamic smem byte offsets (k_main)
#define OFF_WB    77824     // A tile: 128*304 halfs
#define OFF_XI    110592    // wbuf: 2 x 16384 B
#define OFF_AIB0  112768
#define OFF_AIB1  113792
#define OFF_B2    114816
#define OFF_B3    115840
#define SMEM_BYTES 116864
#define SMEM_AJI  110592    // k_aji: A tile + wbuf only

// ---------------- device scratch (static; no allocation) ----------------
__device__ __align__(16) float  d_X[B_ * S_ * SA];
__device__ __align__(16) __half d_Xh[B_ * S_ * 288];   // fragment-permuted fp16 X
__device__ __align__(16) float  d_AJ[B_ * S_ * H_];
__device__ __align__(16) float  d_AI[B_ * S_ * H_];
__device__ __align__(16) float  d_PART[B_ * S_ * H_];
// weights fp16 in per-thread MMA fragment order; chunk = 32k x 256n = 8192 halfs
__device__ __align__(16) __half d_WJf[9 * 8192];
__device__ __align__(16) __half d_WIf[9 * 8192];
__device__ __align__(16) __half d_W1f[9 * 8192];
__device__ __align__(16) __half d_W2f[8 * 8192];
__device__ __align__(16) __half d_W3f[8 * 8192];

// ---------------- helpers ----------------
__device__ __forceinline__ void mma16(float (&d)[4], const uint32_t (&a)[4],
                                      const uint32_t (&b)[2]) {
    asm volatile(
        "mma.sync.aligned.m16n8k16.row.col.f32.f16.f16.f32 "
        "{%0,%1,%2,%3}, {%4,%5,%6,%7}, {%8,%9}, {%0,%1,%2,%3};"
        : "+f"(d[0]), "+f"(d[1]), "+f"(d[2]), "+f"(d[3])
        : "r"(a[0]), "r"(a[1]), "r"(a[2]), "r"(a[3]), "r"(b[0]), "r"(b[1]));
}
__device__ __forceinline__ void cpasync16(uint32_t s, const void* g) {
    asm volatile("cp.async.cg.shared.global [%0], [%1], 16;" :: "r"(s), "l"(g));
}
__device__ __forceinline__ uint32_t h2u(__half2 h) {
    return *(uint32_t*)&h;
}

// ---------------- kernel P: prep (X build + X fragments + weight fragments) --
// blocks [0,32): build d_X (fp32) + d_Xh (fp16 fragment layout), 64 rows each
// blocks [32,75): 43 weight chunks -> fragment layout via smem staging
__global__ void __launch_bounds__(256) k_prep(
    const float* __restrict__ sent, const float* __restrict__ coord,
    const float* __restrict__ gw1, const float* __restrict__ gw2,
    const float* __restrict__ gw3)
{
    __shared__ float Ws[32 * 256];
    int blk = blockIdx.x, tid = threadIdx.x;

    if (blk < 32) {
        int r0 = blk * 64;
        // d_X fp32: 64 rows x 68 float4
#pragma unroll 4
        for (int it = 0; it < 17; it++) {
            int s = tid + it * 256;
            int row = s / 68, c4 = s % 68;
            int bs = r0 + row, k = c4 * 4;
            float4 v = make_float4(0.f, 0.f, 0.f, 0.f);
            if (k < 256) v = *(const float4*)(sent + (size_t)bs * 256 + k);
            else if (k == 256) { v.x = coord[(size_t)bs * 2]; v.y = coord[(size_t)bs * 2 + 1]; }
            *(float4*)(d_X + (size_t)bs * SA + k) = v;
        }
        // d_Xh fragment layout: 64 rows x 18 groups (16 k each)
        uint32_t* Xh32 = (uint32_t*)d_Xh;
        for (int it = 0; it < 5; it++) {
            int e = tid + it * 256;
            if (e >= 64 * 18) break;
            int row = e / 18, gp = e % 18;
            int bs = r0 + row;
            uint4 u0 = make_uint4(0u, 0u, 0u, 0u), u1 = u0;
            if (gp < 17) {
                float p[16];
                if (gp < 16) {
#pragma unroll
                    for (int t = 0; t < 4; t++) {
                        float4 a = *(const float4*)(sent + (size_t)bs * 256 + gp * 16 + t * 4);
                        p[t*4+0] = a.x; p[t*4+1] = a.y; p[t*4+2] = a.z; p[t*4+3] = a.w;
                    }
                } else {
#pragma unroll
                    for (int t = 0; t < 16; t++) p[t] = 0.f;
                    p[0] = coord[(size_t)bs * 2];
                    p[1] = coord[(size_t)bs * 2 + 1];
                }
                uint32_t wv[8];
#pragma unroll
                for (int pp = 0; pp < 8; pp++) {
                    int kk = 2 * (pp >> 1) + 8 * (pp & 1);
                    wv[pp] = h2u(__floats2half2_rn(p[kk], p[kk + 1]));
                }
                u0 = make_uint4(wv[0], wv[1], wv[2], wv[3]);
                u1 = make_uint4(wv[4], wv[5], wv[6], wv[7]);
            }
            uint4* dst = (uint4*)(Xh32 + (size_t)bs * 144 + gp * 8);
            dst[0] = u0; dst[1] = u1;
        }
    } else {
        // weight chunk blocks
        int wb = blk - 32;
        const float* gsrc; int rowoff, c, klim; __half* dstf;
        if (wb < 9)       { gsrc = gw1; rowoff = 0;   c = wb;      klim = KX;  dstf = d_WJf; }
        else if (wb < 18) { gsrc = gw1; rowoff = 258; c = wb - 9;  klim = KX;  dstf = d_WIf; }
        else if (wb < 27) { gsrc = gw1; rowoff = 516; c = wb - 18; klim = KX;  dstf = d_W1f; }
        else if (wb < 35) { gsrc = gw2; rowoff = 0;   c = wb - 27; klim = 256; dstf = d_W2f; }
        else              { gsrc = gw3; rowoff = 0;   c = wb - 35; klim = 256; dstf = d_W3f; }

        // coalesced load 32k x 256n slab
#pragma unroll 8
        for (int it = 0; it < 32; it++) {
            int s = tid + it * 256;
            int kk = s >> 8, n = s & 255;
            int k = c * 32 + kk;
            Ws[s] = (k < klim) ? gsrc[(size_t)(rowoff + k) * 256 + n] : 0.f;
        }
        __syncthreads();

        // write fragment order (coalesced 16B stores)
        uint4* dst4 = (uint4*)(dstf + (size_t)c * 8192);
#pragma unroll
        for (int it = 0; it < 4; it++) {
            int seg = tid + it * 256;       // uint4 index, 8 halfs
            __half hv[8];
#pragma unroll
            for (int x = 0; x < 8; x++) {
                int e = seg * 8 + x;
                int off = e >> 1, h = e & 1;
                int ks = off >> 11, rem = off & 2047;
                int nb = rem >> 6, l2 = rem & 63;
                int lane = l2 >> 1, j = l2 & 1;
                int tg = lane & 3, g = lane >> 2;
                int kk = ks * 16 + j * 8 + 2 * tg + h;
                int n = nb * 8 + g;
                hv[x] = __float2half_rn(Ws[kk * 256 + n]);
            }
            uint4 u;
            u.x = h2u(__halves2half2(hv[0], hv[1]));
            u.y = h2u(__halves2half2(hv[2], hv[3]));
            u.z = h2u(__halves2half2(hv[4], hv[5]));
            u.w = h2u(__halves2half2(hv[6], hv[7]));
            dst4[seg] = u;
        }
    }
}

// ---------------- weight chunk staging: linear 16KB copy (512 thr) -----------
__device__ __forceinline__ void stage_chunk(uint32_t bdst, const __half* __restrict__ W) {
    int tid = threadIdx.x;
#pragma unroll
    for (int it = 0; it < 2; it++) {
        int seg = tid + it * 512;
        cpasync16(bdst + (uint32_t)seg * 16u, (const char*)W + (size_t)seg * 16);
    }
    asm volatile("cp.async.commit_group;");
}

// ---------------- fp16 fragment GEMM: 128x256, 16 warps, warp tile 32x64 -----
__device__ __forceinline__ void gemm_frag(
    float (&acc)[2][8][4],
    const uint32_t* __restrict__ Ap32,
    const uint32_t* __restrict__ wbuf, uint32_t wb_s32,
    const __half* __restrict__ W, int nch, int p0,
    const __half* __restrict__ nextW,
    int wm, int wn, int g, int tg)
{
#pragma unroll
    for (int mi = 0; mi < 2; mi++)
#pragma unroll
        for (int ni = 0; ni < 8; ni++)
#pragma unroll
            for (int q = 0; q < 4; q++) acc[mi][ni][q] = 0.f;

    int lane = threadIdx.x & 31;
    const uint32_t* A0 = Ap32 + (size_t)(wm * 32 + g) * ROW32 + 2 * tg;

    for (int c = 0; c < nch; c++) {
        asm volatile("cp.async.wait_group 0;" ::: "memory");
        __syncthreads();
        if (c + 1 < nch)
            stage_chunk(wb_s32 + (uint32_t)(((c + 1 + p0) & 1)) * 16384u,
                        W + (size_t)(c + 1) * 8192);
        const uint32_t* wb = wbuf + ((c + p0) & 1) * 4096;
#pragma unroll
        for (int ks = 0; ks < 2; ks++) {
            uint32_t a[2][4];
            const uint32_t* ar = A0 + c * 16 + ks * 8;
#pragma unroll
            for (int mi = 0; mi < 2; mi++) {
                uint2 L0 = *(const uint2*)(ar + (size_t)(mi * 16) * ROW32);
                uint2 L1 = *(const uint2*)(ar + (size_t)(mi * 16 + 8) * ROW32);
                a[mi][0] = L0.x; a[mi][1] = L1.x; a[mi][2] = L0.y; a[mi][3] = L1.y;
            }
            const uint32_t* wp = wb + ks * 2048 + (wn * 8) * 64 + lane * 2;
#pragma unroll
            for (int ni = 0; ni < 8; ni++) {
                uint2 bb = *(const uint2*)(wp + ni * 64);
                uint32_t b[2] = {bb.x, bb.y};
                mma16(acc[0][ni], a[0], b);
                mma16(acc[1][ni], a[1], b);
            }
        }
    }
    if (nextW)
        stage_chunk(wb_s32 + (uint32_t)(((nch + p0) & 1)) * 16384u, nextW);
}

// ---------------- kernel AJI: AJ/AI via tensor cores, 32 CTAs -----------------
__global__ void __launch_bounds__(512, 1) k_aji() {
    extern __shared__ char smc[];
    uint32_t* Ap32 = (uint32_t*)smc;
    uint32_t* wbuf = (uint32_t*)(smc + OFF_WB);

    int tid = threadIdx.x;
    int w = tid >> 5, lane = tid & 31;
    int wm = w >> 2, wn = w & 3;
    int g = lane >> 2, tg = lane & 3;
    int rb = blockIdx.x >> 1, half_ = blockIdx.x & 1;

    uint32_t a_s32  = (uint32_t)__cvta_generic_to_shared(Ap32);
    uint32_t wb_s32 = (uint32_t)__cvta_generic_to_shared(wbuf);
    const __half* Wf = half_ ? d_WIf : d_WJf;

    // A tile: 128 rows of d_Xh (576 B each) into stride-608B rows
#pragma unroll 2
    for (int s = tid; s < 128 * 36; s += 512) {
        int row = s / 36, sg = s % 36;
        cpasync16(a_s32 + (uint32_t)(row * 608 + sg * 16),
                  (const char*)d_Xh + (size_t)(rb * 128 + row) * 576 + sg * 16);
    }
    stage_chunk(wb_s32, Wf);   // commit covers the A-tile loads too

    float acc[2][8][4];
    gemm_frag(acc, Ap32, wbuf, wb_s32, Wf, 9, 0, (const __half*)0, wm, wn, g, tg);

    float* dst = half_ ? d_AI : d_AJ;
#pragma unroll
    for (int mi = 0; mi < 2; mi++) {
        int r = wm * 32 + mi * 16 + g;
#pragma unroll
        for (int ni = 0; ni < 8; ni++) {
            int c0 = wn * 64 + ni * 8 + 2 * tg;
            *(float2*)(dst + (size_t)(rb * 128 + r) * H_ + c0) =
                make_float2(acc[mi][ni][0], acc[mi][ni][1]);
            *(float2*)(dst + (size_t)(rb * 128 + r + 8) * H_ + c0) =
                make_float2(acc[mi][ni][2], acc[mi][ni][3]);
        }
    }
}

// ---------------- kernel C: main fused chain, 512 thr, one CTA per (b,ipair) -
__global__ void __launch_bounds__(512, 1) k_main(
    const float* __restrict__ gb1, const float* __restrict__ gb2,
    const float* __restrict__ gb3)
{
    extern __shared__ char smc[];
    uint32_t* Ap32 = (uint32_t*)smc;
    uint32_t* wbuf = (uint32_t*)(smc + OFF_WB);
    float* xi_s = (float*)(smc + OFF_XI);
    float* aib0 = (float*)(smc + OFF_AIB0);
    float* aib1 = (float*)(smc + OFF_AIB1);
    float* b2s  = (float*)(smc + OFF_B2);
    float* b3s  = (float*)(smc + OFF_B3);

    int tid = threadIdx.x;
    int w = tid >> 5, lane = tid & 31;
    int wm = w >> 2, wn = w & 3;
    int g = lane >> 2, tg = lane & 3;
    int b = blockIdx.x >> 5, ip = blockIdx.x & 31;
    int i0 = 2 * ip, i1 = 2 * ip + 1;

    uint32_t wb_s32 = (uint32_t)__cvta_generic_to_shared(wbuf);
    const float* Xb = d_X + (size_t)b * S_ * SA;

    stage_chunk(wb_s32, d_W1f);

    for (int k = tid; k < 2 * SA; k += 512) {
        int half_ = k >= SA, kk = k - half_ * SA;
        xi_s[k] = Xb[(size_t)(half_ ? i1 : i0) * SA + kk];
    }
    if (tid < 256) {
        aib0[tid] = d_AI[(size_t)(b * S_ + i0) * H_ + tid] + gb1[tid];
        aib1[tid] = d_AI[(size_t)(b * S_ + i1) * H_ + tid] + gb1[tid];
        b2s[tid] = gb2[tid];
        b3s[tid] = gb3[tid];
    }
    __syncthreads();

    // build P tile (half, k-permuted fragment layout)
#pragma unroll 1
    for (int q = 0; q < 5; q++) {
        int e = tid + q * 512;
        if (e >= 2304) break;
        int r = e / 18, gp = e % 18;
        int half_ = r >> 6, j = r & 63;
        uint4 u0 = make_uint4(0u, 0u, 0u, 0u), u1 = u0;
        if (gp < 17) {
            const float* xj = Xb + (size_t)j * SA + gp * 16;
            const float* xv = xi_s + half_ * SA + gp * 16;
            float p[16];
#pragma unroll
            for (int t = 0; t < 4; t++) {
                float4 a = *(const float4*)(xj + t * 4);
                float4 c = *(const float4*)(xv + t * 4);
                p[t*4+0] = a.x * c.x; p[t*4+1] = a.y * c.y;
                p[t*4+2] = a.z * c.z; p[t*4+3] = a.w * c.w;
            }
            uint32_t wv[8];
#pragma unroll
            for (int pp = 0; pp < 8; pp++) {
                int kk = 2 * (pp >> 1) + 8 * (pp & 1);
                wv[pp] = h2u(__floats2half2_rn(p[kk], p[kk + 1]));
            }
            u0 = make_uint4(wv[0], wv[1], wv[2], wv[3]);
            u1 = make_uint4(wv[4], wv[5], wv[6], wv[7]);
        }
        uint4* dst = (uint4*)(Ap32 + (size_t)r * ROW32 + gp * 8);
        dst[0] = u0; dst[1] = u1;
    }

    float acc[2][8][4];

    // ======== layer 1 ========
    gemm_frag(acc, Ap32, wbuf, wb_s32, d_W1f, 9, 0, d_W2f, wm, wn, g, tg);
    __syncthreads();
    {
        const float* AJb = d_AJ + (size_t)(b * S_) * H_;
        const float* aibp = (wm >= 2) ? aib1 : aib0;
#pragma unroll
        for (int mi = 0; mi < 2; mi++) {
            int r = wm * 32 + mi * 16 + g;
            int j0 = r & 63;
            const float* AJ0 = AJb + (size_t)j0 * H_;
            const float* AJ1 = AJb + (size_t)(j0 + 8) * H_;
#pragma unroll
            for (int ni = 0; ni < 8; ni++) {
                int c0 = wn * 64 + ni * 8 + 2 * tg;
                float2 aj0 = *(const float2*)(AJ0 + c0);
                float2 aj1 = *(const float2*)(AJ1 + c0);
                float2 ab  = *(const float2*)(aibp + c0);
                float v00 = fmaxf(acc[mi][ni][0] + aj0.x + ab.x, 0.f);
                float v01 = fmaxf(acc[mi][ni][1] + aj0.y + ab.y, 0.f);
                float v10 = fmaxf(acc[mi][ni][2] + aj1.x + ab.x, 0.f);
                float v11 = fmaxf(acc[mi][ni][3] + aj1.y + ab.y, 0.f);
                uint32_t boff = (uint32_t)((wn * 4 + (ni >> 1)) * 8 + 2 * tg + (ni & 1));
                Ap32[(size_t)r * ROW32 + boff]       = h2u(__floats2half2_rn(v00, v01));
                Ap32[(size_t)(r + 8) * ROW32 + boff] = h2u(__floats2half2_rn(v10, v11));
            }
        }
    }

    // ======== layer 2 ========
    gemm_frag(acc, Ap32, wbuf, wb_s32, d_W2f, 8, 1, d_W3f, wm, wn, g, tg);
    __syncthreads();
    {
#pragma unroll
        for (int mi = 0; mi < 2; mi++) {
            int r = wm * 32 + mi * 16 + g;
#pragma unroll
            for (int ni = 0; ni < 8; ni++) {
                int c0 = wn * 64 + ni * 8 + 2 * tg;
                float2 ab = *(const float2*)(b2s + c0);
                float v00 = fmaxf(acc[mi][ni][0] + ab.x, 0.f);
                float v01 = fmaxf(acc[mi][ni][1] + ab.y, 0.f);
                float v10 = fmaxf(acc[mi][ni][2] + ab.x, 0.f);
                float v11 = fmaxf(acc[mi][ni][3] + ab.y, 0.f);
                uint32_t boff = (uint32_t)((wn * 4 + (ni >> 1)) * 8 + 2 * tg + (ni & 1));
                Ap32[(size_t)r * ROW32 + boff]       = h2u(__floats2half2_rn(v00, v01));
                Ap32[(size_t)(r + 8) * ROW32 + boff] = h2u(__floats2half2_rn(v10, v11));
            }
        }
    }

    // ======== layer 3 + row reduction ========
    gemm_frag(acc, Ap32, wbuf, wb_s32, d_W3f, 8, 1, (const __half*)0, wm, wn, g, tg);
    __syncthreads();
    {
#pragma unroll
        for (int mi = 0; mi < 2; mi++) {
            int r = wm * 32 + mi * 16 + g;
#pragma unroll
            for (int ni = 0; ni < 8; ni++) {
                int c0 = wn * 64 + ni * 8 + 2 * tg;
                float2 ab = *(const float2*)(b3s + c0);
                float v00 = fmaxf(acc[mi][ni][0] + ab.x, 0.f);
                float v01 = fmaxf(acc[mi][ni][1] + ab.y, 0.f);
                float v10 = fmaxf(acc[mi][ni][2] + ab.x, 0.f);
                float v11 = fmaxf(acc[mi][ni][3] + ab.y, 0.f);
                Ap32[(size_t)r * ROW32 + (c0 >> 1)]       = h2u(__floats2half2_rn(v00, v01));
                Ap32[(size_t)(r + 8) * ROW32 + (c0 >> 1)] = h2u(__floats2half2_rn(v10, v11));
            }
        }
        __syncthreads();
        const __half* Aph = (const __half*)smc;
        int t = tid & 255, h = tid >> 8;
        float s = 0.f;
#pragma unroll 8
        for (int rr = 0; rr < 64; rr++)
            s += __half2float(Aph[(size_t)(h * 64 + rr) * ROWH + t]);
        d_PART[(size_t)(b * S_ + (h ? i1 : i0)) * H_ + t] = s;
    }
}

// ---------------- kernel D: reduce over i + final MLP (512 thr, split-K) -----
__global__ void __launch_bounds__(512) k_final(
    const float* __restrict__ fw1, const float* __restrict__ fb1,
    const float* __restrict__ fw2, const float* __restrict__ fb2,
    const float* __restrict__ fw3, const float* __restrict__ fb3,
    float* __restrict__ out)
{
    __shared__ float s0[H_], s1[H_], s2[H_], part[512];
    int b = blockIdx.x;
    int t = threadIdx.x & 255, h = threadIdx.x >> 8;

    const float* P = d_PART + (size_t)b * S_ * H_;
    float s = 0.f;
#pragma unroll 8
    for (int i = h * 32; i < h * 32 + 32; i++) s += P[i * H_ + t];
    part[h * 256 + t] = s;
    __syncthreads();
    if (h == 0) s0[t] = part[t] + part[256 + t];
    __syncthreads();

    {
        float a0 = 0.f, a1 = 0.f, a2 = 0.f, a3 = 0.f;
        const float* W = fw1 + (size_t)h * 128 * H_;
        const float* si = s0 + h * 128;
#pragma unroll 8
        for (int k = 0; k < 128; k += 4) {
            a0 += si[k]     * W[(size_t)k * H_ + t];
            a1 += si[k + 1] * W[(size_t)(k + 1) * H_ + t];
            a2 += si[k + 2] * W[(size_t)(k + 2) * H_ + t];
            a3 += si[k + 3] * W[(size_t)(k + 3) * H_ + t];
        }
        part[h * 256 + t] = (a0 + a1) + (a2 + a3);
    }
    __syncthreads();
    if (h == 0) s1[t] = fmaxf(part[t] + part[256 + t] + fb1[t], 0.f);
    __syncthreads();

    {
        float a0 = 0.f, a1 = 0.f, a2 = 0.f, a3 = 0.f;
        const float* W = fw2 + (size_t)h * 128 * H_;
        const float* si = s1 + h * 128;
#pragma unroll 8
        for (int k = 0; k < 128; k += 4) {
            a0 += si[k]     * W[(size_t)k * H_ + t];
            a1 += si[k + 1] * W[(size_t)(k + 1) * H_ + t];
            a2 += si[k + 2] * W[(size_t)(k + 2) * H_ + t];
            a3 += si[k + 3] * W[(size_t)(k + 3) * H_ + t];
        }
        part[h * 256 + t] = (a0 + a1) + (a2 + a3);
    }
    __syncthreads();
    if (h == 0) s2[t] = fmaxf(part[t] + part[256 + t] + fb2[t], 0.f);
    __syncthreads();

    if (t < OUT_) {
        float a = 0.f;
        const float* si = s2 + h * 128;
        const float* W = fw3 + (size_t)h * 128 * OUT_;
#pragma unroll 8
        for (int k = 0; k < 128; k++) a += si[k] * W[(size_t)k * OUT_ + t];
        part[h * 256 + t] = a;
    }
    __syncthreads();
    if (h == 0 && t < OUT_)
        out[b * OUT_ + t] = part[t] + part[256 + t] + fb3[t];
}

// ---------------- launch ----------------
extern "C" void kernel_launch(void* const* d_in, const int* in_sizes, int n_in,
                              void* d_out, int out_size) {
    const float* sent  = (const float*)d_in[0];
    const float* coord = (const float*)d_in[1];
    const float* gw1   = (const float*)d_in[2];
    const float* gb1   = (const float*)d_in[3];
    const float* gw2   = (const float*)d_in[4];
    const float* gb2   = (const float*)d_in[5];
    const float* gw3   = (const float*)d_in[6];
    const float* gb3   = (const float*)d_in[7];
    const float* fw1   = (const float*)d_in[8];
    const float* fb1   = (const float*)d_in[9];
    const float* fw2   = (const float*)d_in[10];
    const float* fb2   = (const float*)d_in[11];
    const float* fw3   = (const float*)d_in[12];
    const float* fb3   = (const float*)d_in[13];
    float* out = (float*)d_out;

    k_prep<<<75, 256>>>(sent, coord, gw1, gw2, gw3);

    cudaFuncSetAttribute(k_aji, cudaFuncAttributeMaxDynamicSharedMemorySize,
                         SMEM_AJI);
    k_aji<<<32, 512, SMEM_AJI>>>();

    cudaFuncSetAttribute(k_main, cudaFuncAttributeMaxDynamicSharedMemorySize,
                         SMEM_BYTES);
    k_main<<<B_ * S_ / 2, 512, SMEM_BYTES>>>(gb1, gb2, gb3);

    k_final<<<B_, 512>>>(fw1, fb1, fw2, fb2, fw3, fb3, out);
}

// round 13
// speedup vs baseline: 4.5991x; 1.0307x over previous
#include <cuda_runtime.h>
#include <cuda_fp16.h>
#include <cstdint>
#include <cstddef>

// Problem constants
#define B_   32
#define S_   64
#define KX   258        // D_MODEL + 2
#define SA   272        // d_X row stride (floats)
#define H_   256
#define OUT_ 10

// A/activation tile: 128 rows x 304 halfs (152 b32/row)
#define ROW32 152
#define ROWH  304

// dynamic smem byte offsets (k_main)
#define OFF_WB    77824     // A tile: 128*304 halfs
#define OFF_XI    110592    // wbuf: 2 x 16384 B
#define OFF_AIB0  112768
#define OFF_AIB1  113792
#define OFF_B2    114816
#define OFF_B3    115840
#define SMEM_BYTES 116864
#define SMEM_AJI  110592    // k_aji: A tile + wbuf only
#define SMEM_MLP  69632     // k_mlp: 2x32KB wbuf + s0/s1/s2 + partials

// ---------------- device scratch (static; no allocation) ----------------
__device__ __align__(16) float  d_X[B_ * S_ * SA];
__device__ __align__(16) __half d_Xh[B_ * S_ * 288];   // fragment-permuted fp16 X
__device__ __align__(16) float  d_AJ[B_ * S_ * H_];
__device__ __align__(16) float  d_AI[B_ * S_ * H_];
__device__ __align__(16) float  d_PART[B_ * S_ * H_];
__device__ __align__(16) float  d_S0[B_ * H_];         // per-batch reduced rel
// weights fp16 in per-thread MMA fragment order; chunk = 32k x 256n = 8192 halfs
__device__ __align__(16) __half d_WJf[9 * 8192];
__device__ __align__(16) __half d_WIf[9 * 8192];
__device__ __align__(16) __half d_W1f[9 * 8192];
__device__ __align__(16) __half d_W2f[8 * 8192];
__device__ __align__(16) __half d_W3f[8 * 8192];

// ---------------- helpers ----------------
__device__ __forceinline__ void mma16(float (&d)[4], const uint32_t (&a)[4],
                                      const uint32_t (&b)[2]) {
    asm volatile(
        "mma.sync.aligned.m16n8k16.row.col.f32.f16.f16.f32 "
        "{%0,%1,%2,%3}, {%4,%5,%6,%7}, {%8,%9}, {%0,%1,%2,%3};"
        : "+f"(d[0]), "+f"(d[1]), "+f"(d[2]), "+f"(d[3])
        : "r"(a[0]), "r"(a[1]), "r"(a[2]), "r"(a[3]), "r"(b[0]), "r"(b[1]));
}
__device__ __forceinline__ void cpasync16(uint32_t s, const void* g) {
    asm volatile("cp.async.cg.shared.global [%0], [%1], 16;" :: "r"(s), "l"(g));
}
__device__ __forceinline__ uint32_t h2u(__half2 h) {
    return *(uint32_t*)&h;
}

// ---------------- kernel P: prep (X build + X fragments + weight fragments) --
__global__ void __launch_bounds__(256) k_prep(
    const float* __restrict__ sent, const float* __restrict__ coord,
    const float* __restrict__ gw1, const float* __restrict__ gw2,
    const float* __restrict__ gw3)
{
    __shared__ float Ws[32 * 256];
    int blk = blockIdx.x, tid = threadIdx.x;

    if (blk < 32) {
        int r0 = blk * 64;
#pragma unroll 4
        for (int it = 0; it < 17; it++) {
            int s = tid + it * 256;
            int row = s / 68, c4 = s % 68;
            int bs = r0 + row, k = c4 * 4;
            float4 v = make_float4(0.f, 0.f, 0.f, 0.f);
            if (k < 256) v = *(const float4*)(sent + (size_t)bs * 256 + k);
            else if (k == 256) { v.x = coord[(size_t)bs * 2]; v.y = coord[(size_t)bs * 2 + 1]; }
            *(float4*)(d_X + (size_t)bs * SA + k) = v;
        }
        uint32_t* Xh32 = (uint32_t*)d_Xh;
        for (int it = 0; it < 5; it++) {
            int e = tid + it * 256;
            if (e >= 64 * 18) break;
            int row = e / 18, gp = e % 18;
            int bs = r0 + row;
            uint4 u0 = make_uint4(0u, 0u, 0u, 0u), u1 = u0;
            if (gp < 17) {
                float p[16];
                if (gp < 16) {
#pragma unroll
                    for (int t = 0; t < 4; t++) {
                        float4 a = *(const float4*)(sent + (size_t)bs * 256 + gp * 16 + t * 4);
                        p[t*4+0] = a.x; p[t*4+1] = a.y; p[t*4+2] = a.z; p[t*4+3] = a.w;
                    }
                } else {
#pragma unroll
                    for (int t = 0; t < 16; t++) p[t] = 0.f;
                    p[0] = coord[(size_t)bs * 2];
                    p[1] = coord[(size_t)bs * 2 + 1];
                }
                uint32_t wv[8];
#pragma unroll
                for (int pp = 0; pp < 8; pp++) {
                    int kk = 2 * (pp >> 1) + 8 * (pp & 1);
                    wv[pp] = h2u(__floats2half2_rn(p[kk], p[kk + 1]));
                }
                u0 = make_uint4(wv[0], wv[1], wv[2], wv[3]);
                u1 = make_uint4(wv[4], wv[5], wv[6], wv[7]);
            }
            uint4* dst = (uint4*)(Xh32 + (size_t)bs * 144 + gp * 8);
            dst[0] = u0; dst[1] = u1;
        }
    } else {
        int wb = blk - 32;
        const float* gsrc; int rowoff, c, klim; __half* dstf;
        if (wb < 9)       { gsrc = gw1; rowoff = 0;   c = wb;      klim = KX;  dstf = d_WJf; }
        else if (wb < 18) { gsrc = gw1; rowoff = 258; c = wb - 9;  klim = KX;  dstf = d_WIf; }
        else if (wb < 27) { gsrc = gw1; rowoff = 516; c = wb - 18; klim = KX;  dstf = d_W1f; }
        else if (wb < 35) { gsrc = gw2; rowoff = 0;   c = wb - 27; klim = 256; dstf = d_W2f; }
        else              { gsrc = gw3; rowoff = 0;   c = wb - 35; klim = 256; dstf = d_W3f; }

#pragma unroll 8
        for (int it = 0; it < 32; it++) {
            int s = tid + it * 256;
            int kk = s >> 8, n = s & 255;
            int k = c * 32 + kk;
            Ws[s] = (k < klim) ? gsrc[(size_t)(rowoff + k) * 256 + n] : 0.f;
        }
        __syncthreads();

        uint4* dst4 = (uint4*)(dstf + (size_t)c * 8192);
#pragma unroll
        for (int it = 0; it < 4; it++) {
            int seg = tid + it * 256;
            __half hv[8];
#pragma unroll
            for (int x = 0; x < 8; x++) {
                int e = seg * 8 + x;
                int off = e >> 1, h = e & 1;
                int ks = off >> 11, rem = off & 2047;
                int nb = rem >> 6, l2 = rem & 63;
                int lane = l2 >> 1, j = l2 & 1;
                int tg = lane & 3, g = lane >> 2;
                int kk = ks * 16 + j * 8 + 2 * tg + h;
                int n = nb * 8 + g;
                hv[x] = __float2half_rn(Ws[kk * 256 + n]);
            }
            uint4 u;
            u.x = h2u(__halves2half2(hv[0], hv[1]));
            u.y = h2u(__halves2half2(hv[2], hv[3]));
            u.z = h2u(__halves2half2(hv[4], hv[5]));
            u.w = h2u(__halves2half2(hv[6], hv[7]));
            dst4[seg] = u;
        }
    }
}

// ---------------- weight chunk staging: linear 16KB copy (512 thr) -----------
__device__ __forceinline__ void stage_chunk(uint32_t bdst, const __half* __restrict__ W) {
    int tid = threadIdx.x;
#pragma unroll
    for (int it = 0; it < 2; it++) {
        int seg = tid + it * 512;
        cpasync16(bdst + (uint32_t)seg * 16u, (const char*)W + (size_t)seg * 16);
    }
    asm volatile("cp.async.commit_group;");
}

// ---------------- fp16 fragment GEMM: 128x256, 16 warps, warp tile 32x64 -----
__device__ __forceinline__ void gemm_frag(
    float (&acc)[2][8][4],
    const uint32_t* __restrict__ Ap32,
    const uint32_t* __restrict__ wbuf, uint32_t wb_s32,
    const __half* __restrict__ W, int nch, int p0,
    const __half* __restrict__ nextW,
    int wm, int wn, int g, int tg)
{
#pragma unroll
    for (int mi = 0; mi < 2; mi++)
#pragma unroll
        for (int ni = 0; ni < 8; ni++)
#pragma unroll
            for (int q = 0; q < 4; q++) acc[mi][ni][q] = 0.f;

    int lane = threadIdx.x & 31;
    const uint32_t* A0 = Ap32 + (size_t)(wm * 32 + g) * ROW32 + 2 * tg;

    for (int c = 0; c < nch; c++) {
        asm volatile("cp.async.wait_group 0;" ::: "memory");
        __syncthreads();
        if (c + 1 < nch)
            stage_chunk(wb_s32 + (uint32_t)(((c + 1 + p0) & 1)) * 16384u,
                        W + (size_t)(c + 1) * 8192);
        const uint32_t* wb = wbuf + ((c + p0) & 1) * 4096;
#pragma unroll
        for (int ks = 0; ks < 2; ks++) {
            uint32_t a[2][4];
            const uint32_t* ar = A0 + c * 16 + ks * 8;
#pragma unroll
            for (int mi = 0; mi < 2; mi++) {
                uint2 L0 = *(const uint2*)(ar + (size_t)(mi * 16) * ROW32);
                uint2 L1 = *(const uint2*)(ar + (size_t)(mi * 16 + 8) * ROW32);
                a[mi][0] = L0.x; a[mi][1] = L1.x; a[mi][2] = L0.y; a[mi][3] = L1.y;
            }
            const uint32_t* wp = wb + ks * 2048 + (wn * 8) * 64 + lane * 2;
#pragma unroll
            for (int ni = 0; ni < 8; ni++) {
                uint2 bb = *(const uint2*)(wp + ni * 64);
                uint32_t b[2] = {bb.x, bb.y};
                mma16(acc[0][ni], a[0], b);
                mma16(acc[1][ni], a[1], b);
            }
        }
    }
    if (nextW)
        stage_chunk(wb_s32 + (uint32_t)(((nch + p0) & 1)) * 16384u, nextW);
}

// ---------------- kernel AJI: AJ/AI via tensor cores, 32 CTAs -----------------
__global__ void __launch_bounds__(512, 1) k_aji() {
    extern __shared__ char smc[];
    uint32_t* Ap32 = (uint32_t*)smc;
    uint32_t* wbuf = (uint32_t*)(smc + OFF_WB);

    int tid = threadIdx.x;
    int w = tid >> 5, lane = tid & 31;
    int wm = w >> 2, wn = w & 3;
    int g = lane >> 2, tg = lane & 3;
    int rb = blockIdx.x >> 1, half_ = blockIdx.x & 1;

    uint32_t a_s32  = (uint32_t)__cvta_generic_to_shared(Ap32);
    uint32_t wb_s32 = (uint32_t)__cvta_generic_to_shared(wbuf);
    const __half* Wf = half_ ? d_WIf : d_WJf;

#pragma unroll 2
    for (int s = tid; s < 128 * 36; s += 512) {
        int row = s / 36, sg = s % 36;
        cpasync16(a_s32 + (uint32_t)(row * 608 + sg * 16),
                  (const char*)d_Xh + (size_t)(rb * 128 + row) * 576 + sg * 16);
    }
    stage_chunk(wb_s32, Wf);

    float acc[2][8][4];
    gemm_frag(acc, Ap32, wbuf, wb_s32, Wf, 9, 0, (const __half*)0, wm, wn, g, tg);

    float* dst = half_ ? d_AI : d_AJ;
#pragma unroll
    for (int mi = 0; mi < 2; mi++) {
        int r = wm * 32 + mi * 16 + g;
#pragma unroll
        for (int ni = 0; ni < 8; ni++) {
            int c0 = wn * 64 + ni * 8 + 2 * tg;
            *(float2*)(dst + (size_t)(rb * 128 + r) * H_ + c0) =
                make_float2(acc[mi][ni][0], acc[mi][ni][1]);
            *(float2*)(dst + (size_t)(rb * 128 + r + 8) * H_ + c0) =
                make_float2(acc[mi][ni][2], acc[mi][ni][3]);
        }
    }
}

// ---------------- kernel C: main fused chain, 512 thr, one CTA per (b,ipair) -
__global__ void __launch_bounds__(512, 1) k_main(
    const float* __restrict__ gb1, const float* __restrict__ gb2,
    const float* __restrict__ gb3)
{
    extern __shared__ char smc[];
    uint32_t* Ap32 = (uint32_t*)smc;
    uint32_t* wbuf = (uint32_t*)(smc + OFF_WB);
    float* xi_s = (float*)(smc + OFF_XI);
    float* aib0 = (float*)(smc + OFF_AIB0);
    float* aib1 = (float*)(smc + OFF_AIB1);
    float* b2s  = (float*)(smc + OFF_B2);
    float* b3s  = (float*)(smc + OFF_B3);

    int tid = threadIdx.x;
    int w = tid >> 5, lane = tid & 31;
    int wm = w >> 2, wn = w & 3;
    int g = lane >> 2, tg = lane & 3;
    int b = blockIdx.x >> 5, ip = blockIdx.x & 31;
    int i0 = 2 * ip, i1 = 2 * ip + 1;

    uint32_t wb_s32 = (uint32_t)__cvta_generic_to_shared(wbuf);
    const float* Xb = d_X + (size_t)b * S_ * SA;

    stage_chunk(wb_s32, d_W1f);

    for (int k = tid; k < 2 * SA; k += 512) {
        int half_ = k >= SA, kk = k - half_ * SA;
        xi_s[k] = Xb[(size_t)(half_ ? i1 : i0) * SA + kk];
    }
    if (tid < 256) {
        aib0[tid] = d_AI[(size_t)(b * S_ + i0) * H_ + tid] + gb1[tid];
        aib1[tid] = d_AI[(size_t)(b * S_ + i1) * H_ + tid] + gb1[tid];
        b2s[tid] = gb2[tid];
        b3s[tid] = gb3[tid];
    }
    __syncthreads();

#pragma unroll 1
    for (int q = 0; q < 5; q++) {
        int e = tid + q * 512;
        if (e >= 2304) break;
        int r = e / 18, gp = e % 18;
        int half_ = r >> 6, j = r & 63;
        uint4 u0 = make_uint4(0u, 0u, 0u, 0u), u1 = u0;
        if (gp < 17) {
            const float* xj = Xb + (size_t)j * SA + gp * 16;
            const float* xv = xi_s + half_ * SA + gp * 16;
            float p[16];
#pragma unroll
            for (int t = 0; t < 4; t++) {
                float4 a = *(const float4*)(xj + t * 4);
                float4 c = *(const float4*)(xv + t * 4);
                p[t*4+0] = a.x * c.x; p[t*4+1] = a.y * c.y;
                p[t*4+2] = a.z * c.z; p[t*4+3] = a.w * c.w;
            }
            uint32_t wv[8];
#pragma unroll
            for (int pp = 0; pp < 8; pp++) {
                int kk = 2 * (pp >> 1) + 8 * (pp & 1);
                wv[pp] = h2u(__floats2half2_rn(p[kk], p[kk + 1]));
            }
            u0 = make_uint4(wv[0], wv[1], wv[2], wv[3]);
            u1 = make_uint4(wv[4], wv[5], wv[6], wv[7]);
        }
        uint4* dst = (uint4*)(Ap32 + (size_t)r * ROW32 + gp * 8);
        dst[0] = u0; dst[1] = u1;
    }

    float acc[2][8][4];

    // ======== layer 1 ========
    gemm_frag(acc, Ap32, wbuf, wb_s32, d_W1f, 9, 0, d_W2f, wm, wn, g, tg);
    __syncthreads();
    {
        const float* AJb = d_AJ + (size_t)(b * S_) * H_;
        const float* aibp = (wm >= 2) ? aib1 : aib0;
#pragma unroll
        for (int mi = 0; mi < 2; mi++) {
            int r = wm * 32 + mi * 16 + g;
            int j0 = r & 63;
            const float* AJ0 = AJb + (size_t)j0 * H_;
            const float* AJ1 = AJb + (size_t)(j0 + 8) * H_;
#pragma unroll
            for (int ni = 0; ni < 8; ni++) {
                int c0 = wn * 64 + ni * 8 + 2 * tg;
                float2 aj0 = *(const float2*)(AJ0 + c0);
                float2 aj1 = *(const float2*)(AJ1 + c0);
                float2 ab  = *(const float2*)(aibp + c0);
                float v00 = fmaxf(acc[mi][ni][0] + aj0.x + ab.x, 0.f);
                float v01 = fmaxf(acc[mi][ni][1] + aj0.y + ab.y, 0.f);
                float v10 = fmaxf(acc[mi][ni][2] + aj1.x + ab.x, 0.f);
                float v11 = fmaxf(acc[mi][ni][3] + aj1.y + ab.y, 0.f);
                uint32_t boff = (uint32_t)((wn * 4 + (ni >> 1)) * 8 + 2 * tg + (ni & 1));
                Ap32[(size_t)r * ROW32 + boff]       = h2u(__floats2half2_rn(v00, v01));
                Ap32[(size_t)(r + 8) * ROW32 + boff] = h2u(__floats2half2_rn(v10, v11));
            }
        }
    }

    // ======== layer 2 ========
    gemm_frag(acc, Ap32, wbuf, wb_s32, d_W2f, 8, 1, d_W3f, wm, wn, g, tg);
    __syncthreads();
    {
#pragma unroll
        for (int mi = 0; mi < 2; mi++) {
            int r = wm * 32 + mi * 16 + g;
#pragma unroll
            for (int ni = 0; ni < 8; ni++) {
                int c0 = wn * 64 + ni * 8 + 2 * tg;
                float2 ab = *(const float2*)(b2s + c0);
                float v00 = fmaxf(acc[mi][ni][0] + ab.x, 0.f);
                float v01 = fmaxf(acc[mi][ni][1] + ab.y, 0.f);
                float v10 = fmaxf(acc[mi][ni][2] + ab.x, 0.f);
                float v11 = fmaxf(acc[mi][ni][3] + ab.y, 0.f);
                uint32_t boff = (uint32_t)((wn * 4 + (ni >> 1)) * 8 + 2 * tg + (ni & 1));
                Ap32[(size_t)r * ROW32 + boff]       = h2u(__floats2half2_rn(v00, v01));
                Ap32[(size_t)(r + 8) * ROW32 + boff] = h2u(__floats2half2_rn(v10, v11));
            }
        }
    }

    // ======== layer 3 + row reduction ========
    gemm_frag(acc, Ap32, wbuf, wb_s32, d_W3f, 8, 1, (const __half*)0, wm, wn, g, tg);
    __syncthreads();
    {
#pragma unroll
        for (int mi = 0; mi < 2; mi++) {
            int r = wm * 32 + mi * 16 + g;
#pragma unroll
            for (int ni = 0; ni < 8; ni++) {
                int c0 = wn * 64 + ni * 8 + 2 * tg;
                float2 ab = *(const float2*)(b3s + c0);
                float v00 = fmaxf(acc[mi][ni][0] + ab.x, 0.f);
                float v01 = fmaxf(acc[mi][ni][1] + ab.y, 0.f);
                float v10 = fmaxf(acc[mi][ni][2] + ab.x, 0.f);
                float v11 = fmaxf(acc[mi][ni][3] + ab.y, 0.f);
                Ap32[(size_t)r * ROW32 + (c0 >> 1)]       = h2u(__floats2half2_rn(v00, v01));
                Ap32[(size_t)(r + 8) * ROW32 + (c0 >> 1)] = h2u(__floats2half2_rn(v10, v11));
            }
        }
        __syncthreads();
        const __half* Aph = (const __half*)smc;
        int t = tid & 255, h = tid >> 8;
        float s = 0.f;
#pragma unroll 8
        for (int rr = 0; rr < 64; rr++)
            s += __half2float(Aph[(size_t)(h * 64 + rr) * ROWH + t]);
        d_PART[(size_t)(b * S_ + (h ? i1 : i0)) * H_ + t] = s;
    }
}

// ---------------- kernel R: reduce d_PART over i (parallel, LDG.128) ---------
__global__ void __launch_bounds__(256) k_reduce() {
    __shared__ float4 sm4[256];
    int b = blockIdx.x >> 2, cs = blockIdx.x & 3;
    int t = threadIdx.x, c4 = t & 15, rg = t >> 4;

    const float4* P4 = (const float4*)(d_PART + (size_t)b * S_ * H_) + cs * 16 + c4;
    float4 v0 = P4[(size_t)rg * 64];
    float4 v1 = P4[(size_t)(rg + 16) * 64];
    float4 v2 = P4[(size_t)(rg + 32) * 64];
    float4 v3 = P4[(size_t)(rg + 48) * 64];
    float4 s;
    s.x = (v0.x + v1.x) + (v2.x + v3.x);
    s.y = (v0.y + v1.y) + (v2.y + v3.y);
    s.z = (v0.z + v1.z) + (v2.z + v3.z);
    s.w = (v0.w + v1.w) + (v2.w + v3.w);
    sm4[t] = s;
    __syncthreads();
#pragma unroll
    for (int off = 8; off > 0; off >>= 1) {
        if (rg < off) {
            float4 a = sm4[t], bb = sm4[t + off * 16];
            a.x += bb.x; a.y += bb.y; a.z += bb.z; a.w += bb.w;
            sm4[t] = a;
        }
        __syncthreads();
    }
    if (rg == 0)
        ((float4*)(d_S0 + (size_t)b * H_ + cs * 64))[c4] = sm4[c4];
}

// ---------------- k_mlp: final MLP with cp.async-staged weights --------------
__device__ __forceinline__ void stage_mlp(uint32_t bdst, const float* __restrict__ W) {
    int tid = threadIdx.x;
#pragma unroll
    for (int it = 0; it < 8; it++) {
        int seg = tid + it * 256;
        cpasync16(bdst + (uint32_t)seg * 16u, W + (size_t)seg * 4);
    }
    asm volatile("cp.async.commit_group;");
}

__device__ __forceinline__ float mlp_layer(
    const float* __restrict__ wsm, uint32_t w_s32,
    const float* __restrict__ sin, const float* __restrict__ Wg,
    const float* __restrict__ nextW, int t, int p0)
{
    float a0 = 0.f, a1 = 0.f, a2 = 0.f, a3 = 0.f;
    for (int c = 0; c < 8; c++) {
        asm volatile("cp.async.wait_group 0;" ::: "memory");
        __syncthreads();
        if (c < 7)
            stage_mlp(w_s32 + (uint32_t)(((c + 1 + p0) & 1)) * 32768u,
                      Wg + (size_t)(c + 1) * 8192);
        else if (nextW)
            stage_mlp(w_s32 + (uint32_t)(((8 + p0) & 1)) * 32768u, nextW);
        const float* W = wsm + ((c + p0) & 1) * 8192;
        const float* s = sin + c * 32;
#pragma unroll
        for (int kk = 0; kk < 32; kk += 4) {
            a0 += s[kk]     * W[(kk)     * 256 + t];
            a1 += s[kk + 1] * W[(kk + 1) * 256 + t];
            a2 += s[kk + 2] * W[(kk + 2) * 256 + t];
            a3 += s[kk + 3] * W[(kk + 3) * 256 + t];
        }
    }
    return (a0 + a1) + (a2 + a3);
}

__global__ void __launch_bounds__(256) k_mlp(
    const float* __restrict__ fw1, const float* __restrict__ fb1,
    const float* __restrict__ fw2, const float* __restrict__ fb2,
    const float* __restrict__ fw3, const float* __restrict__ fb3,
    float* __restrict__ out)
{
    extern __shared__ char smc[];
    float* wsm = (float*)smc;                 // 2 x 8192 floats
    float* s0  = (float*)(smc + 65536);
    float* s1  = s0 + 256;
    float* s2  = s1 + 256;
    float* pp  = s2 + 256;                    // 160 floats

    int b = blockIdx.x, t = threadIdx.x;
    uint32_t w_s32 = (uint32_t)__cvta_generic_to_shared(wsm);

    stage_mlp(w_s32, fw1);                    // fw1 chunk 0 -> buf 0
    s0[t] = d_S0[(size_t)b * H_ + t];
    // layer 1 (p0=0); prefetch fw2 chunk0 into buf 0 at the end
    float r1 = mlp_layer(wsm, w_s32, s0, fw1, fw2, t, 0);
    s1[t] = fmaxf(r1 + fb1[t], 0.f);
    // layer 2 (p0=0)
    float r2 = mlp_layer(wsm, w_s32, s1, fw2, (const float*)0, t, 0);
    s2[t] = fmaxf(r2 + fb2[t], 0.f);

    // layer 3: stage fw3 (2560 floats) into buf 0 (free: last chunk was buf 1)
    for (int seg = t; seg < 640; seg += 256)
        cpasync16(w_s32 + (uint32_t)seg * 16u, fw3 + (size_t)seg * 4);
    asm volatile("cp.async.commit_group;");
    asm volatile("cp.async.wait_group 0;" ::: "memory");
    __syncthreads();

    if (t < 160) {
        int o = t % 10, h = t / 10;           // 16 k-slices of 16
        float a = 0.f;
#pragma unroll
        for (int k = 0; k < 16; k++)
            a += s2[h * 16 + k] * wsm[(h * 16 + k) * 10 + o];
        pp[t] = a;
    }
    __syncthreads();
    if (t < OUT_) {
        float a = fb3[t];
#pragma unroll
        for (int h = 0; h < 16; h++) a += pp[h * 10 + t];
        out[b * OUT_ + t] = a;
    }
}

// ---------------- launch ----------------
extern "C" void kernel_launch(void* const* d_in, const int* in_sizes, int n_in,
                              void* d_out, int out_size) {
    const float* sent  = (const float*)d_in[0];
    const float* coord = (const float*)d_in[1];
    const float* gw1   = (const float*)d_in[2];
    const float* gb1   = (const float*)d_in[3];
    const float* gw2   = (const float*)d_in[4];
    const float* gb2   = (const float*)d_in[5];
    const float* gw3   = (const float*)d_in[6];
    const float* gb3   = (const float*)d_in[7];
    const float* fw1   = (const float*)d_in[8];
    const float* fb1   = (const float*)d_in[9];
    const float* fw2   = (const float*)d_in[10];
    const float* fb2   = (const float*)d_in[11];
    const float* fw3   = (const float*)d_in[12];
    const float* fb3   = (const float*)d_in[13];
    float* out = (float*)d_out;

    k_prep<<<75, 256>>>(sent, coord, gw1, gw2, gw3);

    cudaFuncSetAttribute(k_aji, cudaFuncAttributeMaxDynamicSharedMemorySize,
                         SMEM_AJI);
    k_aji<<<32, 512, SMEM_AJI>>>();

    cudaFuncSetAttribute(k_main, cudaFuncAttributeMaxDynamicSharedMemorySize,
                         SMEM_BYTES);
    k_main<<<B_ * S_ / 2, 512, SMEM_BYTES>>>(gb1, gb2, gb3);

    k_reduce<<<B_ * 4, 256>>>();

    cudaFuncSetAttribute(k_mlp, cudaFuncAttributeMaxDynamicSharedMemorySize,
                         SMEM_MLP);
    k_mlp<<<B_, 256, SMEM_MLP>>>(fw1, fb1, fw2, fb2, fw3, fb3, out);
}

// round 14
// speedup vs baseline: 4.6809x; 1.0178x over previous
#include <cuda_runtime.h>
#include <cuda_fp16.h>
#include <cstdint>
#include <cstddef>

// Problem constants
#define B_   32
#define S_   64
#define KX   258        // D_MODEL + 2
#define SA   272        // d_X row stride (floats)
#define H_   256
#define OUT_ 10

// A/activation tile: 128 rows x 336 halfs (168 b32/row; 168%32==8 ->
// LDS.64 phases g0..3 / g4..7 hit banks 8g+2tg, conflict-free)
#define ROW32 168
#define ROWH  336

// dynamic smem byte offsets (k_main)
#define OFF_WB    86016     // A tile: 128*336 halfs
#define OFF_XI    151552    // wbuf: 2 x 32768 B
#define OFF_AIB0  153728
#define OFF_AIB1  154752
#define OFF_B2    155776
#define OFF_B3    156800
#define SMEM_BYTES 157824
#define SMEM_AJI  151552    // k_aji: A tile + wbuf only
#define SMEM_MLP  69632

// ---------------- device scratch (static; no allocation) ----------------
__device__ __align__(16) float  d_X[B_ * S_ * SA];
__device__ __align__(16) __half d_Xh[B_ * S_ * 288];   // fragment-permuted fp16 X
__device__ __align__(16) float  d_AJ[B_ * S_ * H_];
__device__ __align__(16) float  d_AI[B_ * S_ * H_];
__device__ __align__(16) float  d_PART[B_ * S_ * H_];
__device__ __align__(16) float  d_S0[B_ * H_];
// weights fp16 in fragment order; 32k-sub-chunk = 8192 halfs; layer1 padded to 320 K
__device__ __align__(16) __half d_WJf[10 * 8192];
__device__ __align__(16) __half d_WIf[10 * 8192];
__device__ __align__(16) __half d_W1f[10 * 8192];
__device__ __align__(16) __half d_W2f[8 * 8192];
__device__ __align__(16) __half d_W3f[8 * 8192];

// ---------------- helpers ----------------
__device__ __forceinline__ void mma16(float (&d)[4], const uint32_t (&a)[4],
                                      const uint32_t (&b)[2]) {
    asm volatile(
        "mma.sync.aligned.m16n8k16.row.col.f32.f16.f16.f32 "
        "{%0,%1,%2,%3}, {%4,%5,%6,%7}, {%8,%9}, {%0,%1,%2,%3};"
        : "+f"(d[0]), "+f"(d[1]), "+f"(d[2]), "+f"(d[3])
        : "r"(a[0]), "r"(a[1]), "r"(a[2]), "r"(a[3]), "r"(b[0]), "r"(b[1]));
}
__device__ __forceinline__ void cpasync16(uint32_t s, const void* g) {
    asm volatile("cp.async.cg.shared.global [%0], [%1], 16;" :: "r"(s), "l"(g));
}
__device__ __forceinline__ uint32_t h2u(__half2 h) {
    return *(uint32_t*)&h;
}

// ---------------- kernel P: prep (X build + X fragments + weight fragments) --
__global__ void __launch_bounds__(256) k_prep(
    const float* __restrict__ sent, const float* __restrict__ coord,
    const float* __restrict__ gw1, const float* __restrict__ gw2,
    const float* __restrict__ gw3)
{
    __shared__ float Ws[32 * 256];
    int blk = blockIdx.x, tid = threadIdx.x;

    if (blk < 32) {
        int r0 = blk * 64;
#pragma unroll 4
        for (int it = 0; it < 17; it++) {
            int s = tid + it * 256;
            int row = s / 68, c4 = s % 68;
            int bs = r0 + row, k = c4 * 4;
            float4 v = make_float4(0.f, 0.f, 0.f, 0.f);
            if (k < 256) v = *(const float4*)(sent + (size_t)bs * 256 + k);
            else if (k == 256) { v.x = coord[(size_t)bs * 2]; v.y = coord[(size_t)bs * 2 + 1]; }
            *(float4*)(d_X + (size_t)bs * SA + k) = v;
        }
        uint32_t* Xh32 = (uint32_t*)d_Xh;
        for (int it = 0; it < 5; it++) {
            int e = tid + it * 256;
            if (e >= 64 * 18) break;
            int row = e / 18, gp = e % 18;
            int bs = r0 + row;
            uint4 u0 = make_uint4(0u, 0u, 0u, 0u), u1 = u0;
            if (gp < 17) {
                float p[16];
                if (gp < 16) {
#pragma unroll
                    for (int t = 0; t < 4; t++) {
                        float4 a = *(const float4*)(sent + (size_t)bs * 256 + gp * 16 + t * 4);
                        p[t*4+0] = a.x; p[t*4+1] = a.y; p[t*4+2] = a.z; p[t*4+3] = a.w;
                    }
                } else {
#pragma unroll
                    for (int t = 0; t < 16; t++) p[t] = 0.f;
                    p[0] = coord[(size_t)bs * 2];
                    p[1] = coord[(size_t)bs * 2 + 1];
                }
                uint32_t wv[8];
#pragma unroll
                for (int pp = 0; pp < 8; pp++) {
                    int kk = 2 * (pp >> 1) + 8 * (pp & 1);
                    wv[pp] = h2u(__floats2half2_rn(p[kk], p[kk + 1]));
                }
                u0 = make_uint4(wv[0], wv[1], wv[2], wv[3]);
                u1 = make_uint4(wv[4], wv[5], wv[6], wv[7]);
            }
            uint4* dst = (uint4*)(Xh32 + (size_t)bs * 144 + gp * 8);
            dst[0] = u0; dst[1] = u1;
        }
    } else {
        int wb = blk - 32;
        const float* gsrc; int rowoff, c, klim; __half* dstf;
        if (wb < 10)      { gsrc = gw1; rowoff = 0;   c = wb;      klim = KX;  dstf = d_WJf; }
        else if (wb < 20) { gsrc = gw1; rowoff = 258; c = wb - 10; klim = KX;  dstf = d_WIf; }
        else if (wb < 30) { gsrc = gw1; rowoff = 516; c = wb - 20; klim = KX;  dstf = d_W1f; }
        else if (wb < 38) { gsrc = gw2; rowoff = 0;   c = wb - 30; klim = 256; dstf = d_W2f; }
        else              { gsrc = gw3; rowoff = 0;   c = wb - 38; klim = 256; dstf = d_W3f; }

#pragma unroll 8
        for (int it = 0; it < 32; it++) {
            int s = tid + it * 256;
            int kk = s >> 8, n = s & 255;
            int k = c * 32 + kk;
            Ws[s] = (k < klim) ? gsrc[(size_t)(rowoff + k) * 256 + n] : 0.f;
        }
        __syncthreads();

        uint4* dst4 = (uint4*)(dstf + (size_t)c * 8192);
#pragma unroll
        for (int it = 0; it < 4; it++) {
            int seg = tid + it * 256;
            __half hv[8];
#pragma unroll
            for (int x = 0; x < 8; x++) {
                int e = seg * 8 + x;
                int off = e >> 1, h = e & 1;
                int ks = off >> 11, rem = off & 2047;
                int nb = rem >> 6, l2 = rem & 63;
                int lane = l2 >> 1, j = l2 & 1;
                int tg = lane & 3, g = lane >> 2;
                int kk = ks * 16 + j * 8 + 2 * tg + h;
                int n = nb * 8 + g;
                hv[x] = __float2half_rn(Ws[kk * 256 + n]);
            }
            uint4 u;
            u.x = h2u(__halves2half2(hv[0], hv[1]));
            u.y = h2u(__halves2half2(hv[2], hv[3]));
            u.z = h2u(__halves2half2(hv[4], hv[5]));
            u.w = h2u(__halves2half2(hv[6], hv[7]));
            dst4[seg] = u;
        }
    }
}

// ---------------- weight chunk staging: linear 32KB copy (512 thr) -----------
__device__ __forceinline__ void stage_chunk(uint32_t bdst, const __half* __restrict__ W) {
    int tid = threadIdx.x;
#pragma unroll
    for (int it = 0; it < 4; it++) {
        int seg = tid + it * 512;
        cpasync16(bdst + (uint32_t)seg * 16u, (const char*)W + (size_t)seg * 16);
    }
    asm volatile("cp.async.commit_group;");
}

// ---------------- fp16 fragment GEMM: 128x256, KC=64, 16 warps ---------------
__device__ __forceinline__ void gemm_frag(
    float (&acc)[2][8][4],
    const uint32_t* __restrict__ Ap32,
    const uint32_t* __restrict__ wbuf, uint32_t wb_s32,
    const __half* __restrict__ W, int nch, int p0,
    const __half* __restrict__ nextW,
    int wm, int wn, int g, int tg)
{
#pragma unroll
    for (int mi = 0; mi < 2; mi++)
#pragma unroll
        for (int ni = 0; ni < 8; ni++)
#pragma unroll
            for (int q = 0; q < 4; q++) acc[mi][ni][q] = 0.f;

    int lane = threadIdx.x & 31;
    const uint32_t* A0 = Ap32 + (size_t)(wm * 32 + g) * ROW32 + 2 * tg;

    for (int c = 0; c < nch; c++) {
        asm volatile("cp.async.wait_group 0;" ::: "memory");
        __syncthreads();
        if (c + 1 < nch)
            stage_chunk(wb_s32 + (uint32_t)(((c + 1 + p0) & 1)) * 32768u,
                        W + (size_t)(c + 1) * 16384);
        const uint32_t* wb = wbuf + ((c + p0) & 1) * 8192;
#pragma unroll
        for (int ks = 0; ks < 4; ks++) {
            uint32_t a[2][4];
            const uint32_t* ar = A0 + c * 32 + ks * 8;
#pragma unroll
            for (int mi = 0; mi < 2; mi++) {
                uint2 L0 = *(const uint2*)(ar + (size_t)(mi * 16) * ROW32);
                uint2 L1 = *(const uint2*)(ar + (size_t)(mi * 16 + 8) * ROW32);
                a[mi][0] = L0.x; a[mi][1] = L1.x; a[mi][2] = L0.y; a[mi][3] = L1.y;
            }
            const uint32_t* wp = wb + ks * 2048 + wn * 512 + lane * 2;
#pragma unroll
            for (int ni = 0; ni < 8; ni++) {
                uint2 bb = *(const uint2*)(wp + ni * 64);
                uint32_t b[2] = {bb.x, bb.y};
                mma16(acc[0][ni], a[0], b);
                mma16(acc[1][ni], a[1], b);
            }
        }
    }
    if (nextW)
        stage_chunk(wb_s32 + (uint32_t)(((nch + p0) & 1)) * 32768u, nextW);
}

// ---------------- kernel AJI: AJ/AI via tensor cores, 32 CTAs -----------------
__global__ void __launch_bounds__(512, 1) k_aji() {
    extern __shared__ char smc[];
    uint32_t* Ap32 = (uint32_t*)smc;
    uint32_t* wbuf = (uint32_t*)(smc + OFF_WB);

    int tid = threadIdx.x;
    int w = tid >> 5, lane = tid & 31;
    int wm = w >> 2, wn = w & 3;
    int g = lane >> 2, tg = lane & 3;
    int rb = blockIdx.x >> 1, half_ = blockIdx.x & 1;

    uint32_t a_s32  = (uint32_t)__cvta_generic_to_shared(Ap32);
    uint32_t wb_s32 = (uint32_t)__cvta_generic_to_shared(wbuf);
    const __half* Wf = half_ ? d_WIf : d_WJf;

    // A tile: 128 rows of d_Xh (576 B) into stride-672B rows; zero groups 18,19
#pragma unroll 2
    for (int s = tid; s < 128 * 36; s += 512) {
        int row = s / 36, sg = s % 36;
        cpasync16(a_s32 + (uint32_t)(row * 672 + sg * 16),
                  (const char*)d_Xh + (size_t)(rb * 128 + row) * 576 + sg * 16);
    }
    {
        int row = tid >> 2, q4 = tid & 3;
        ((uint4*)(Ap32 + (size_t)row * ROW32 + 144))[q4] = make_uint4(0u, 0u, 0u, 0u);
    }
    stage_chunk(wb_s32, Wf);

    float acc[2][8][4];
    gemm_frag(acc, Ap32, wbuf, wb_s32, Wf, 5, 0, (const __half*)0, wm, wn, g, tg);

    float* dst = half_ ? d_AI : d_AJ;
#pragma unroll
    for (int mi = 0; mi < 2; mi++) {
        int r = wm * 32 + mi * 16 + g;
#pragma unroll
        for (int ni = 0; ni < 8; ni++) {
            int c0 = wn * 64 + ni * 8 + 2 * tg;
            *(float2*)(dst + (size_t)(rb * 128 + r) * H_ + c0) =
                make_float2(acc[mi][ni][0], acc[mi][ni][1]);
            *(float2*)(dst + (size_t)(rb * 128 + r + 8) * H_ + c0) =
                make_float2(acc[mi][ni][2], acc[mi][ni][3]);
        }
    }
}

// ---------------- kernel C: main fused chain, 512 thr, one CTA per (b,ipair) -
__global__ void __launch_bounds__(512, 1) k_main(
    const float* __restrict__ gb1, const float* __restrict__ gb2,
    const float* __restrict__ gb3)
{
    extern __shared__ char smc[];
    uint32_t* Ap32 = (uint32_t*)smc;
    uint32_t* wbuf = (uint32_t*)(smc + OFF_WB);
    float* xi_s = (float*)(smc + OFF_XI);
    float* aib0 = (float*)(smc + OFF_AIB0);
    float* aib1 = (float*)(smc + OFF_AIB1);
    float* b2s  = (float*)(smc + OFF_B2);
    float* b3s  = (float*)(smc + OFF_B3);

    int tid = threadIdx.x;
    int w = tid >> 5, lane = tid & 31;
    int wm = w >> 2, wn = w & 3;
    int g = lane >> 2, tg = lane & 3;
    int b = blockIdx.x >> 5, ip = blockIdx.x & 31;
    int i0 = 2 * ip, i1 = 2 * ip + 1;

    uint32_t wb_s32 = (uint32_t)__cvta_generic_to_shared(wbuf);
    const float* Xb = d_X + (size_t)b * S_ * SA;

    stage_chunk(wb_s32, d_W1f);

    for (int k = tid; k < 2 * SA; k += 512) {
        int half_ = k >= SA, kk = k - half_ * SA;
        xi_s[k] = Xb[(size_t)(half_ ? i1 : i0) * SA + kk];
    }
    if (tid < 256) {
        aib0[tid] = d_AI[(size_t)(b * S_ + i0) * H_ + tid] + gb1[tid];
        aib1[tid] = d_AI[(size_t)(b * S_ + i1) * H_ + tid] + gb1[tid];
        b2s[tid] = gb2[tid];
        b3s[tid] = gb3[tid];
    }
    __syncthreads();

    // build P tile (half, k-permuted fragment layout), 128 rows x 20 groups
#pragma unroll 1
    for (int q = 0; q < 5; q++) {
        int e = tid + q * 512;              // exactly 2560
        int r = e / 20, gp = e % 20;
        int half_ = r >> 6, j = r & 63;
        uint4 u0 = make_uint4(0u, 0u, 0u, 0u), u1 = u0;
        if (gp < 17) {
            const float* xj = Xb + (size_t)j * SA + gp * 16;
            const float* xv = xi_s + half_ * SA + gp * 16;
            float p[16];
#pragma unroll
            for (int t = 0; t < 4; t++) {
                float4 a = *(const float4*)(xj + t * 4);
                float4 c = *(const float4*)(xv + t * 4);
                p[t*4+0] = a.x * c.x; p[t*4+1] = a.y * c.y;
                p[t*4+2] = a.z * c.z; p[t*4+3] = a.w * c.w;
            }
            uint32_t wv[8];
#pragma unroll
            for (int pp = 0; pp < 8; pp++) {
                int kk = 2 * (pp >> 1) + 8 * (pp & 1);
                wv[pp] = h2u(__floats2half2_rn(p[kk], p[kk + 1]));
            }
            u0 = make_uint4(wv[0], wv[1], wv[2], wv[3]);
            u1 = make_uint4(wv[4], wv[5], wv[6], wv[7]);
        }
        uint4* dst = (uint4*)(Ap32 + (size_t)r * ROW32 + gp * 8);
        dst[0] = u0; dst[1] = u1;
    }

    float acc[2][8][4];

    // ======== layer 1 (K padded to 320 = 5 chunks of 64) ========
    gemm_frag(acc, Ap32, wbuf, wb_s32, d_W1f, 5, 0, d_W2f, wm, wn, g, tg);
    __syncthreads();
    {
        const float* AJb = d_AJ + (size_t)(b * S_) * H_;
        const float* aibp = (wm >= 2) ? aib1 : aib0;
#pragma unroll
        for (int mi = 0; mi < 2; mi++) {
            int r = wm * 32 + mi * 16 + g;
            int j0 = r & 63;
            const float* AJ0 = AJb + (size_t)j0 * H_;
            const float* AJ1 = AJb + (size_t)(j0 + 8) * H_;
#pragma unroll
            for (int ni = 0; ni < 8; ni++) {
                int c0 = wn * 64 + ni * 8 + 2 * tg;
                float2 aj0 = *(const float2*)(AJ0 + c0);
                float2 aj1 = *(const float2*)(AJ1 + c0);
                float2 ab  = *(const float2*)(aibp + c0);
                float v00 = fmaxf(acc[mi][ni][0] + aj0.x + ab.x, 0.f);
                float v01 = fmaxf(acc[mi][ni][1] + aj0.y + ab.y, 0.f);
                float v10 = fmaxf(acc[mi][ni][2] + aj1.x + ab.x, 0.f);
                float v11 = fmaxf(acc[mi][ni][3] + aj1.y + ab.y, 0.f);
                uint32_t boff = (uint32_t)((wn * 4 + (ni >> 1)) * 8 + 2 * tg + (ni & 1));
                Ap32[(size_t)r * ROW32 + boff]       = h2u(__floats2half2_rn(v00, v01));
                Ap32[(size_t)(r + 8) * ROW32 + boff] = h2u(__floats2half2_rn(v10, v11));
            }
        }
    }

    // ======== layer 2 (4 chunks of 64) ========
    gemm_frag(acc, Ap32, wbuf, wb_s32, d_W2f, 4, 1, d_W3f, wm, wn, g, tg);
    __syncthreads();
    {
#pragma unroll
        for (int mi = 0; mi < 2; mi++) {
            int r = wm * 32 + mi * 16 + g;
#pragma unroll
            for (int ni = 0; ni < 8; ni++) {
                int c0 = wn * 64 + ni * 8 + 2 * tg;
                float2 ab = *(const float2*)(b2s + c0);
                float v00 = fmaxf(acc[mi][ni][0] + ab.x, 0.f);
                float v01 = fmaxf(acc[mi][ni][1] + ab.y, 0.f);
                float v10 = fmaxf(acc[mi][ni][2] + ab.x, 0.f);
                float v11 = fmaxf(acc[mi][ni][3] + ab.y, 0.f);
                uint32_t boff = (uint32_t)((wn * 4 + (ni >> 1)) * 8 + 2 * tg + (ni & 1));
                Ap32[(size_t)r * ROW32 + boff]       = h2u(__floats2half2_rn(v00, v01));
                Ap32[(size_t)(r + 8) * ROW32 + boff] = h2u(__floats2half2_rn(v10, v11));
            }
        }
    }

    // ======== layer 3 + row reduction ========
    gemm_frag(acc, Ap32, wbuf, wb_s32, d_W3f, 4, 1, (const __half*)0, wm, wn, g, tg);
    __syncthreads();
    {
#pragma unroll
        for (int mi = 0; mi < 2; mi++) {
            int r = wm * 32 + mi * 16 + g;
#pragma unroll
            for (int ni = 0; ni < 8; ni++) {
                int c0 = wn * 64 + ni * 8 + 2 * tg;
                float2 ab = *(const float2*)(b3s + c0);
                float v00 = fmaxf(acc[mi][ni][0] + ab.x, 0.f);
                float v01 = fmaxf(acc[mi][ni][1] + ab.y, 0.f);
                float v10 = fmaxf(acc[mi][ni][2] + ab.x, 0.f);
                float v11 = fmaxf(acc[mi][ni][3] + ab.y, 0.f);
                Ap32[(size_t)r * ROW32 + (c0 >> 1)]       = h2u(__floats2half2_rn(v00, v01));
                Ap32[(size_t)(r + 8) * ROW32 + (c0 >> 1)] = h2u(__floats2half2_rn(v10, v11));
            }
        }
        __syncthreads();
        const __half* Aph = (const __half*)smc;
        int t = tid & 255, h = tid >> 8;
        float s = 0.f;
#pragma unroll 8
        for (int rr = 0; rr < 64; rr++)
            s += __half2float(Aph[(size_t)(h * 64 + rr) * ROWH + t]);
        d_PART[(size_t)(b * S_ + (h ? i1 : i0)) * H_ + t] = s;
    }
}

// ---------------- kernel R: reduce d_PART over i (parallel, LDG.128) ---------
__global__ void __launch_bounds__(256) k_reduce() {
    __shared__ float4 sm4[256];
    int b = blockIdx.x >> 2, cs = blockIdx.x & 3;
    int t = threadIdx.x, c4 = t & 15, rg = t >> 4;

    const float4* P4 = (const float4*)(d_PART + (size_t)b * S_ * H_) + cs * 16 + c4;
    float4 v0 = P4[(size_t)rg * 64];
    float4 v1 = P4[(size_t)(rg + 16) * 64];
    float4 v2 = P4[(size_t)(rg + 32) * 64];
    float4 v3 = P4[(size_t)(rg + 48) * 64];
    float4 s;
    s.x = (v0.x + v1.x) + (v2.x + v3.x);
    s.y = (v0.y + v1.y) + (v2.y + v3.y);
    s.z = (v0.z + v1.z) + (v2.z + v3.z);
    s.w = (v0.w + v1.w) + (v2.w + v3.w);
    sm4[t] = s;
    __syncthreads();
#pragma unroll
    for (int off = 8; off > 0; off >>= 1) {
        if (rg < off) {
            float4 a = sm4[t], bb = sm4[t + off * 16];
            a.x += bb.x; a.y += bb.y; a.z += bb.z; a.w += bb.w;
            sm4[t] = a;
        }
        __syncthreads();
    }
    if (rg == 0)
        ((float4*)(d_S0 + (size_t)b * H_ + cs * 64))[c4] = sm4[c4];
}

// ---------------- k_mlp: final MLP with cp.async-staged weights --------------
__device__ __forceinline__ void stage_mlp(uint32_t bdst, const float* __restrict__ W) {
    int tid = threadIdx.x;
#pragma unroll
    for (int it = 0; it < 8; it++) {
        int seg = tid + it * 256;
        cpasync16(bdst + (uint32_t)seg * 16u, W + (size_t)seg * 4);
    }
    asm volatile("cp.async.commit_group;");
}

__device__ __forceinline__ float mlp_layer(
    const float* __restrict__ wsm, uint32_t w_s32,
    const float* __restrict__ sin, const float* __restrict__ Wg,
    const float* __restrict__ nextW, int t, int p0)
{
    float a0 = 0.f, a1 = 0.f, a2 = 0.f, a3 = 0.f;
    for (int c = 0; c < 8; c++) {
        asm volatile("cp.async.wait_group 0;" ::: "memory");
        __syncthreads();
        if (c < 7)
            stage_mlp(w_s32 + (uint32_t)(((c + 1 + p0) & 1)) * 32768u,
                      Wg + (size_t)(c + 1) * 8192);
        else if (nextW)
            stage_mlp(w_s32 + (uint32_t)(((8 + p0) & 1)) * 32768u, nextW);
        const float* W = wsm + ((c + p0) & 1) * 8192;
        const float* s = sin + c * 32;
#pragma unroll
        for (int kk = 0; kk < 32; kk += 4) {
            a0 += s[kk]     * W[(kk)     * 256 + t];
            a1 += s[kk + 1] * W[(kk + 1) * 256 + t];
            a2 += s[kk + 2] * W[(kk + 2) * 256 + t];
            a3 += s[kk + 3] * W[(kk + 3) * 256 + t];
        }
    }
    return (a0 + a1) + (a2 + a3);
}

__global__ void __launch_bounds__(256) k_mlp(
    const float* __restrict__ fw1, const float* __restrict__ fb1,
    const float* __restrict__ fw2, const float* __restrict__ fb2,
    const float* __restrict__ fw3, const float* __restrict__ fb3,
    float* __restrict__ out)
{
    extern __shared__ char smc[];
    float* wsm = (float*)smc;
    float* s0  = (float*)(smc + 65536);
    float* s1  = s0 + 256;
    float* s2  = s1 + 256;
    float* pp  = s2 + 256;

    int b = blockIdx.x, t = threadIdx.x;
    uint32_t w_s32 = (uint32_t)__cvta_generic_to_shared(wsm);

    stage_mlp(w_s32, fw1);
    s0[t] = d_S0[(size_t)b * H_ + t];
    float r1 = mlp_layer(wsm, w_s32, s0, fw1, fw2, t, 0);
    s1[t] = fmaxf(r1 + fb1[t], 0.f);
    float r2 = mlp_layer(wsm, w_s32, s1, fw2, (const float*)0, t, 0);
    s2[t] = fmaxf(r2 + fb2[t], 0.f);

    for (int seg = t; seg < 640; seg += 256)
        cpasync16(w_s32 + (uint32_t)seg * 16u, fw3 + (size_t)seg * 4);
    asm volatile("cp.async.commit_group;");
    asm volatile("cp.async.wait_group 0;" ::: "memory");
    __syncthreads();

    if (t < 160) {
        int o = t % 10, h = t / 10;
        float a = 0.f;
#pragma unroll
        for (int k = 0; k < 16; k++)
            a += s2[h * 16 + k] * wsm[(h * 16 + k) * 10 + o];
        pp[t] = a;
    }
    __syncthreads();
    if (t < OUT_) {
        float a = fb3[t];
#pragma unroll
        for (int h = 0; h < 16; h++) a += pp[h * 10 + t];
        out[b * OUT_ + t] = a;
    }
}

// ---------------- launch ----------------
extern "C" void kernel_launch(void* const* d_in, const int* in_sizes, int n_in,
                              void* d_out, int out_size) {
    const float* sent  = (const float*)d_in[0];
    const float* coord = (const float*)d_in[1];
    const float* gw1   = (const float*)d_in[2];
    const float* gb1   = (const float*)d_in[3];
    const float* gw2   = (const float*)d_in[4];
    const float* gb2   = (const float*)d_in[5];
    const float* gw3   = (const float*)d_in[6];
    const float* gb3   = (const float*)d_in[7];
    const float* fw1   = (const float*)d_in[8];
    const float* fb1   = (const float*)d_in[9];
    const float* fw2   = (const float*)d_in[10];
    const float* fb2   = (const float*)d_in[11];
    const float* fw3   = (const float*)d_in[12];
    const float* fb3   = (const float*)d_in[13];
    float* out = (float*)d_out;

    k_prep<<<78, 256>>>(sent, coord, gw1, gw2, gw3);

    cudaFuncSetAttribute(k_aji, cudaFuncAttributeMaxDynamicSharedMemorySize,
                         SMEM_AJI);
    k_aji<<<32, 512, SMEM_AJI>>>();

    cudaFuncSetAttribute(k_main, cudaFuncAttributeMaxDynamicSharedMemorySize,
                         SMEM_BYTES);
    k_main<<<B_ * S_ / 2, 512, SMEM_BYTES>>>(gb1, gb2, gb3);

    k_reduce<<<B_ * 4, 256>>>();

    cudaFuncSetAttribute(k_mlp, cudaFuncAttributeMaxDynamicSharedMemorySize,
                         SMEM_MLP);
    k_mlp<<<B_, 256, SMEM_MLP>>>(fw1, fb1, fw2, fb2, fw3, fb3, out);
}